// round 6
// baseline (speedup 1.0000x reference)
#include <cuda_runtime.h>
#include <cstdint>
#include <cstddef>

// Problem constants
#define Bv   128
#define Tv   512
#define Vv   32000
#define Ev   256
#define Hv   128
#define G4H  512      // 4*H (gate columns per direction)
#define NW   1024     // 4H * 2 directions (concat fw|bw)

// Scratch: embW = emb @ [W_fw | W_bw] + [b_fw | b_bw]   (131 MB, device global)
__device__ float g_embW[(size_t)Vv * NW];
// tokens dtype flag: 1 if int64 layout, 0 if int32
__device__ int g_tok64;

// ---------------------------------------------------------------------------
// Kernel 0: detect tokens dtype. If int64, every odd 32-bit word (high half)
// is 0 (tokens < 32000). If int32, odd words are random tokens (~0 zeros).
// Reads only the first 65536 int32 words = minimum footprint of either layout.
// ---------------------------------------------------------------------------
__global__ void detect_tok_kernel(const unsigned int* __restrict__ w) {
    __shared__ int cnt;
    if (threadIdx.x == 0) cnt = 0;
    __syncthreads();
    int local = 0;
    for (int i = threadIdx.x; i < (Bv * Tv / 2); i += blockDim.x)
        if (w[2 * i + 1] == 0u) local++;
    atomicAdd(&cnt, local);
    __syncthreads();
    if (threadIdx.x == 0) g_tok64 = (cnt > (Bv * Tv / 4)) ? 1 : 0;
}

// ---------------------------------------------------------------------------
// Kernel 1: embW[v][n] = sum_k emb[v][k] * W[k][n] + bias[n]
// M=32000, K=256, N=1024 (cols 0..511 from W_fw/b_fw, 512..1023 from W_bw/b_bw)
// 128x128 tile, BK=8, 256 threads, 8x8 per thread, reg-prefetched k-tiles.
// ---------------------------------------------------------------------------
__global__ __launch_bounds__(256) void embw_gemm_kernel(
    const float* __restrict__ emb,
    const float* __restrict__ Wfw, const float* __restrict__ Wbw,
    const float* __restrict__ bfw, const float* __restrict__ bbw)
{
    __shared__ float As[8][128];
    __shared__ float Bs[8][128];

    const int tid = threadIdx.x;
    const int m0 = blockIdx.x * 128;
    const int n0 = blockIdx.y * 128;

    const float* Wp;
    const float* bp;
    int nb;
    if (n0 < G4H) { Wp = Wfw; bp = bfw; nb = n0; }
    else          { Wp = Wbw; bp = bbw; nb = n0 - G4H; }

    const int ar = tid >> 1;          // A row within tile (0..127)
    const int ac = (tid & 1) * 4;     // A col group (0 or 4)
    const int br = tid >> 5;          // B row within k-tile (0..7)
    const int bc = (tid & 31) * 4;    // B col group
    const int tx = tid & 15;
    const int ty = tid >> 4;

    float acc[8][8];
#pragma unroll
    for (int i = 0; i < 8; i++)
#pragma unroll
        for (int jj = 0; jj < 8; jj++) acc[i][jj] = 0.0f;

    // prefetch first k-tile into registers
    float4 av = *(const float4*)&emb[(size_t)(m0 + ar) * Ev + ac];
    float4 bv = *(const float4*)&Wp[(size_t)br * G4H + nb + bc];

    for (int kt = 0; kt < Ev / 8; ++kt) {
        As[ac + 0][ar] = av.x; As[ac + 1][ar] = av.y;
        As[ac + 2][ar] = av.z; As[ac + 3][ar] = av.w;
        *(float4*)&Bs[br][bc] = bv;
        __syncthreads();
        if (kt + 1 < Ev / 8) {
            int k0 = (kt + 1) * 8;
            av = *(const float4*)&emb[(size_t)(m0 + ar) * Ev + k0 + ac];
            bv = *(const float4*)&Wp[(size_t)(k0 + br) * G4H + nb + bc];
        }
#pragma unroll
        for (int kk = 0; kk < 8; ++kk) {
            float a[8], b[8];
            *(float4*)&a[0] = *(const float4*)&As[kk][ty * 8];
            *(float4*)&a[4] = *(const float4*)&As[kk][ty * 8 + 4];
            *(float4*)&b[0] = *(const float4*)&Bs[kk][tx * 8];
            *(float4*)&b[4] = *(const float4*)&Bs[kk][tx * 8 + 4];
#pragma unroll
            for (int i = 0; i < 8; i++)
#pragma unroll
                for (int jj = 0; jj < 8; jj++)
                    acc[i][jj] = fmaf(a[i], b[jj], acc[i][jj]);
        }
        __syncthreads();
    }

    // epilogue: add bias, store
    float bias[8];
    *(float4*)&bias[0] = *(const float4*)&bp[nb + tx * 8];
    *(float4*)&bias[4] = *(const float4*)&bp[nb + tx * 8 + 4];
#pragma unroll
    for (int i = 0; i < 8; i++) {
        int row = m0 + ty * 8 + i;
        float4 v0, v1;
        v0.x = acc[i][0] + bias[0]; v0.y = acc[i][1] + bias[1];
        v0.z = acc[i][2] + bias[2]; v0.w = acc[i][3] + bias[3];
        v1.x = acc[i][4] + bias[4]; v1.y = acc[i][5] + bias[5];
        v1.z = acc[i][6] + bias[6]; v1.w = acc[i][7] + bias[7];
        *(float4*)&g_embW[(size_t)row * NW + n0 + tx * 8]     = v0;
        *(float4*)&g_embW[(size_t)row * NW + n0 + tx * 8 + 4] = v1;
    }
}

// ---------------------------------------------------------------------------
// Kernel 2: persistent LSTM recurrence.
// grid = 128 blocks: blockIdx.x&1 = direction, >>1 = batch group (2 rows).
// 512 threads: thread j owns z-column j. U[:,j]: k<64 in registers,
// k>=64 in SMEM (128 KB). h broadcast from SMEM. embW rows gathered+prefetched.
// ---------------------------------------------------------------------------
__device__ __forceinline__ float sigmoid_f(float x) {
    return 1.0f / (1.0f + __expf(-x));
}
__device__ __forceinline__ float tanh_f(float x) {
    float e = __expf(-2.0f * fabsf(x));
    float t = (1.0f - e) / (1.0f + e);
    return copysignf(t, x);
}

#define LSTM_SMEM_BYTES ((64 * G4H + 1024 + 256 + 1024) * 4)

__global__ __launch_bounds__(512, 1) void lstm_kernel(
    const void*  __restrict__ tokens,
    const float* __restrict__ Ufw,
    const float* __restrict__ Ubw,
    float* __restrict__ out)
{
    extern __shared__ float smem[];
    float* Us   = smem;                    // [64][512] U rows 64..127
    float* zbuf = smem + 64 * G4H;         // [512][2] activated gates
    float* hbuf = zbuf + 1024;             // [128][2] hidden state
    int*   tokb = (int*)(hbuf + 256);      // [2][512] tokens for this block

    const int j   = threadIdx.x;
    const int dir = blockIdx.x & 1;
    const int grp = blockIdx.x >> 1;
    const int b0  = grp * 2;
    const float* U = dir ? Ubw : Ufw;

    // U[k][j] for k in [0,64) -> registers
    float Ur[64];
#pragma unroll
    for (int k = 0; k < 64; k++) Ur[k] = U[k * G4H + j];

    // U rows 64..127 -> SMEM (contiguous copy)
    for (int idx = j; idx < 64 * G4H; idx += 512) Us[idx] = U[64 * G4H + idx];

    // tokens for rows b0, b0+1
    const int is64 = g_tok64;
    for (int idx = j; idx < 2 * Tv; idx += 512) {
        int r = idx >> 9;
        int t = idx & (Tv - 1);
        int tok;
        if (is64) tok = (int)((const long long*)tokens)[(size_t)(b0 + r) * Tv + t];
        else      tok =       ((const int*)tokens)      [(size_t)(b0 + r) * Tv + t];
        tokb[idx] = tok;
    }
    if (j < 128) { hbuf[j * 2] = 0.0f; hbuf[j * 2 + 1] = 0.0f; }
    __syncthreads();

    const int cbase = dir * G4H;
    float c0 = 0.0f, c1 = 0.0f, hl0 = 0.0f, hl1 = 0.0f;

    int t0 = dir ? (Tv - 1) : 0;
    float xw0 = g_embW[(size_t)tokb[t0] * NW + cbase + j];
    float xw1 = g_embW[(size_t)tokb[Tv + t0] * NW + cbase + j];

    for (int s = 0; s < Tv; ++s) {
        const int tc = dir ? (Tv - 1 - s) : s;

        // prefetch next step's input projection rows (hidden behind FMA loop)
        float nx0 = 0.0f, nx1 = 0.0f;
        if (s + 1 < Tv) {
            int tn = dir ? (tc - 1) : (tc + 1);
            nx0 = g_embW[(size_t)tokb[tn] * NW + cbase + j];
            nx1 = g_embW[(size_t)tokb[Tv + tn] * NW + cbase + j];
        }

        float a0 = xw0, a1 = xw1;
#pragma unroll
        for (int k = 0; k < 64; k += 2) {
            float4 hh = *(const float4*)&hbuf[k * 2];   // h[k][0..1], h[k+1][0..1]
            a0 = fmaf(hh.x, Ur[k],     a0);
            a1 = fmaf(hh.y, Ur[k],     a1);
            a0 = fmaf(hh.z, Ur[k + 1], a0);
            a1 = fmaf(hh.w, Ur[k + 1], a1);
        }
#pragma unroll
        for (int k = 64; k < 128; k += 2) {
            float4 hh = *(const float4*)&hbuf[k * 2];
            float u0 = Us[(k - 64) * G4H + j];
            float u1 = Us[(k - 63) * G4H + j];
            a0 = fmaf(hh.x, u0, a0);
            a1 = fmaf(hh.y, u0, a1);
            a0 = fmaf(hh.z, u1, a0);
            a1 = fmaf(hh.w, u1, a1);
        }

        // activations: i,f,o -> sigmoid (j<256 or j>=384), g -> tanh
        float g0, g1;
        if ((j < 256) || (j >= 384)) { g0 = sigmoid_f(a0); g1 = sigmoid_f(a1); }
        else                         { g0 = tanh_f(a0);    g1 = tanh_f(a1);    }
        *(float2*)&zbuf[j * 2] = make_float2(g0, g1);
        __syncthreads();

        if (j < 128) {
            float i0 = zbuf[j * 2],           i1 = zbuf[j * 2 + 1];
            float f0 = zbuf[(j + 128) * 2],   f1 = zbuf[(j + 128) * 2 + 1];
            float gg0 = zbuf[(j + 256) * 2],  gg1 = zbuf[(j + 256) * 2 + 1];
            float o0 = zbuf[(j + 384) * 2],   o1 = zbuf[(j + 384) * 2 + 1];
            c0 = fmaf(f0, c0, i0 * gg0);
            c1 = fmaf(f1, c1, i1 * gg1);
            hl0 = o0 * tanh_f(c0);
            hl1 = o1 * tanh_f(c1);
            hbuf[j * 2]     = hl0;
            hbuf[j * 2 + 1] = hl1;
            out[((size_t)b0 * Tv + tc) * 256 + dir * 128 + j]       = hl0;
            out[((size_t)(b0 + 1) * Tv + tc) * 256 + dir * 128 + j] = hl1;
        }
        __syncthreads();
        xw0 = nx0;
        xw1 = nx1;
    }

    // final states: layout after out[B,T,2H]: h_fw, c_fw, h_bw, c_bw (each [B,H])
    if (j < 128) {
        size_t fin  = (size_t)Bv * Tv * 256;
        size_t hoff = fin + (size_t)(dir * 2) * (Bv * Hv);
        out[hoff + (size_t)b0 * Hv + j]                 = hl0;
        out[hoff + (size_t)(b0 + 1) * Hv + j]           = hl1;
        out[hoff + Bv * Hv + (size_t)b0 * Hv + j]       = c0;
        out[hoff + Bv * Hv + (size_t)(b0 + 1) * Hv + j] = c1;
    }
}

// ---------------------------------------------------------------------------
// Inputs (metadata order): tokens, emb, W_fw, U_fw, b_fw, W_bw, U_bw, b_bw
// Output: out[B,T,2H] fp32, then h_fw, c_fw, h_bw, c_bw (each [B,H])
// ---------------------------------------------------------------------------
extern "C" void kernel_launch(void* const* d_in, const int* in_sizes, int n_in,
                              void* d_out, int out_size)
{
    const void*  tokens = d_in[0];
    const float* emb = (const float*)d_in[1];
    const float* Wfw = (const float*)d_in[2];
    const float* Ufw = (const float*)d_in[3];
    const float* bfw = (const float*)d_in[4];
    const float* Wbw = (const float*)d_in[5];
    const float* Ubw = (const float*)d_in[6];
    const float* bbw = (const float*)d_in[7];
    float* out = (float*)d_out;

    (void)in_sizes; (void)n_in; (void)out_size;

    detect_tok_kernel<<<1, 256>>>((const unsigned int*)tokens);

    dim3 ggrid(Vv / 128, NW / 128);
    embw_gemm_kernel<<<ggrid, 256>>>(emb, Wfw, Wbw, bfw, bbw);

    cudaFuncSetAttribute(lstm_kernel,
                         cudaFuncAttributeMaxDynamicSharedMemorySize,
                         LSTM_SMEM_BYTES);
    lstm_kernel<<<128, 512, LSTM_SMEM_BYTES>>>(tokens, Ufw, Ubw, out);
}

// round 7
// speedup vs baseline: 1.0375x; 1.0375x over previous
#include <cuda_runtime.h>
#include <cstdint>
#include <cstddef>

// Problem constants
#define Bv   128
#define Tv   512
#define Vv   32000
#define Ev   256
#define Hv   128
#define G4H  512      // 4*H (gate columns per direction)
#define NW   1024     // 4H * 2 directions (concat fw|bw)

// Scratch: embW = emb @ [W_fw | W_bw] + [b_fw | b_bw]   (131 MB, device global)
__device__ float g_embW[(size_t)Vv * NW];
// tokens dtype flag: 1 if int64 layout, 0 if int32
__device__ int g_tok64;

// ---------------------------------------------------------------------------
// f32x2 packed-math helpers (sm_103a; ptxas never emits FFMA2 from C++)
// ---------------------------------------------------------------------------
__device__ __forceinline__ unsigned long long fma2(unsigned long long a,
                                                   unsigned long long b,
                                                   unsigned long long c) {
    unsigned long long d;
    asm("fma.rn.f32x2 %0, %1, %2, %3;" : "=l"(d) : "l"(a), "l"(b), "l"(c));
    return d;
}
__device__ __forceinline__ unsigned long long dup2(float x) {
    unsigned long long d;
    asm("mov.b64 %0, {%1, %1};" : "=l"(d) : "f"(x));
    return d;
}
__device__ __forceinline__ unsigned long long pack2(float lo, float hi) {
    unsigned long long d;
    asm("mov.b64 %0, {%1, %2};" : "=l"(d) : "f"(lo), "f"(hi));
    return d;
}
__device__ __forceinline__ void unpack2(unsigned long long v, float& lo, float& hi) {
    asm("mov.b64 {%0, %1}, %2;" : "=f"(lo), "=f"(hi) : "l"(v));
}

// ---------------------------------------------------------------------------
// Kernel 0: detect tokens dtype. If int64, every odd 32-bit word (high half)
// is 0 (tokens < 32000). If int32, odd words are random tokens (~0 zeros).
// ---------------------------------------------------------------------------
__global__ void detect_tok_kernel(const unsigned int* __restrict__ w) {
    __shared__ int cnt;
    if (threadIdx.x == 0) cnt = 0;
    __syncthreads();
    int local = 0;
    for (int i = threadIdx.x; i < (Bv * Tv / 2); i += blockDim.x)
        if (w[2 * i + 1] == 0u) local++;
    atomicAdd(&cnt, local);
    __syncthreads();
    if (threadIdx.x == 0) g_tok64 = (cnt > (Bv * Tv / 4)) ? 1 : 0;
}

// ---------------------------------------------------------------------------
// Kernel 1: embW[v][n] = sum_k emb[v][k] * W[k][n] + bias[n]
// M=32000, K=256, N=1024. 128x128 tile, BK=8, 256 threads, 8x8 per thread.
// Inner product in packed f32x2: 32 FFMA2 + 8 ALU packs per kk (was 64 FFMA).
// ---------------------------------------------------------------------------
__global__ __launch_bounds__(256) void embw_gemm_kernel(
    const float* __restrict__ emb,
    const float* __restrict__ Wfw, const float* __restrict__ Wbw,
    const float* __restrict__ bfw, const float* __restrict__ bbw)
{
    __shared__ float As[8][128];
    __shared__ float Bs[8][128];

    const int tid = threadIdx.x;
    const int m0 = blockIdx.x * 128;
    const int n0 = blockIdx.y * 128;

    const float* Wp;
    const float* bp;
    int nb;
    if (n0 < G4H) { Wp = Wfw; bp = bfw; nb = n0; }
    else          { Wp = Wbw; bp = bbw; nb = n0 - G4H; }

    const int ar = tid >> 1;          // A row within tile (0..127)
    const int ac = (tid & 1) * 4;     // A col group (0 or 4)
    const int br = tid >> 5;          // B row within k-tile (0..7)
    const int bc = (tid & 31) * 4;    // B col group
    const int tx = tid & 15;
    const int ty = tid >> 4;

    unsigned long long acc[8][4];     // acc[i][j2] = packed (col 2*j2, 2*j2+1)
#pragma unroll
    for (int i = 0; i < 8; i++)
#pragma unroll
        for (int j2 = 0; j2 < 4; j2++) acc[i][j2] = 0ull;

    // prefetch first k-tile into registers
    float4 av = *(const float4*)&emb[(size_t)(m0 + ar) * Ev + ac];
    float4 bv = *(const float4*)&Wp[(size_t)br * G4H + nb + bc];

    for (int kt = 0; kt < Ev / 8; ++kt) {
        As[ac + 0][ar] = av.x; As[ac + 1][ar] = av.y;
        As[ac + 2][ar] = av.z; As[ac + 3][ar] = av.w;
        *(float4*)&Bs[br][bc] = bv;
        __syncthreads();
        if (kt + 1 < Ev / 8) {
            int k0 = (kt + 1) * 8;
            av = *(const float4*)&emb[(size_t)(m0 + ar) * Ev + k0 + ac];
            bv = *(const float4*)&Wp[(size_t)(k0 + br) * G4H + nb + bc];
        }
#pragma unroll
        for (int kk = 0; kk < 8; ++kk) {
            float a[8];
            *(float4*)&a[0] = *(const float4*)&As[kk][ty * 8];
            *(float4*)&a[4] = *(const float4*)&As[kk][ty * 8 + 4];
            ulonglong2 b0 = *(const ulonglong2*)&Bs[kk][tx * 8];
            ulonglong2 b1 = *(const ulonglong2*)&Bs[kk][tx * 8 + 4];
#pragma unroll
            for (int i = 0; i < 8; i++) {
                unsigned long long ad = dup2(a[i]);
                acc[i][0] = fma2(ad, b0.x, acc[i][0]);
                acc[i][1] = fma2(ad, b0.y, acc[i][1]);
                acc[i][2] = fma2(ad, b1.x, acc[i][2]);
                acc[i][3] = fma2(ad, b1.y, acc[i][3]);
            }
        }
        __syncthreads();
    }

    // epilogue: unpack, add bias, store
    float bias[8];
    *(float4*)&bias[0] = *(const float4*)&bp[nb + tx * 8];
    *(float4*)&bias[4] = *(const float4*)&bp[nb + tx * 8 + 4];
#pragma unroll
    for (int i = 0; i < 8; i++) {
        int row = m0 + ty * 8 + i;
        float c[8];
#pragma unroll
        for (int j2 = 0; j2 < 4; j2++)
            unpack2(acc[i][j2], c[2 * j2], c[2 * j2 + 1]);
        float4 v0, v1;
        v0.x = c[0] + bias[0]; v0.y = c[1] + bias[1];
        v0.z = c[2] + bias[2]; v0.w = c[3] + bias[3];
        v1.x = c[4] + bias[4]; v1.y = c[5] + bias[5];
        v1.z = c[6] + bias[6]; v1.w = c[7] + bias[7];
        *(float4*)&g_embW[(size_t)row * NW + n0 + tx * 8]     = v0;
        *(float4*)&g_embW[(size_t)row * NW + n0 + tx * 8 + 4] = v1;
    }
}

// ---------------------------------------------------------------------------
// Kernel 2: persistent LSTM recurrence, packed-f32x2 across the 2 batch rows.
// grid = 128 blocks: blockIdx.x&1 = direction, >>1 = batch group (2 rows).
// 512 threads: thread j owns z-column j. Accumulator = f32x2 (row0, row1).
// U[:,j]: k<88 in registers (dup-packed at use, ALU pipe), k>=88 in SMEM
// (40 rows, 80 KB). h broadcast from SMEM as ulonglong2 (naturally paired).
// ---------------------------------------------------------------------------
__device__ __forceinline__ float sigmoid_f(float x) {
    return 1.0f / (1.0f + __expf(-x));
}
__device__ __forceinline__ float tanh_f(float x) {
    float e = __expf(-2.0f * fabsf(x));
    float t = (1.0f - e) / (1.0f + e);
    return copysignf(t, x);
}

#define UREG   88                       // U k-rows held in registers
#define UROWS  (Hv - UREG)              // 40 rows in smem
#define UQ     (UROWS / 4)              // 10 float4 groups per thread
#define LSTM_SMEM_BYTES ((UROWS * G4H + 1024 + 256 + 1024) * 4)

__global__ __launch_bounds__(512, 1) void lstm_kernel(
    const void*  __restrict__ tokens,
    const float* __restrict__ Ufw,
    const float* __restrict__ Ubw,
    float* __restrict__ out)
{
    extern __shared__ float smem[];
    float* Usf  = smem;                     // [UQ][512][4] u quads, rows 88..127
    float* zbuf = smem + UROWS * G4H;       // [512][2] activated gates
    float* hbuf = zbuf + 1024;              // [128][2] hidden state (interleaved)
    int*   tokb = (int*)(hbuf + 256);       // [2][512] tokens for this block

    const int j   = threadIdx.x;
    const int dir = blockIdx.x & 1;
    const int grp = blockIdx.x >> 1;
    const int b0  = grp * 2;
    const float* U = dir ? Ubw : Ufw;

    // U[k][j] for k in [0,UREG) -> registers
    float Ur[UREG];
#pragma unroll
    for (int k = 0; k < UREG; k++) Ur[k] = U[k * G4H + j];

    // U rows UREG..127 -> SMEM as per-thread float4 quads:
    // Usf[q*2048 + col*4 + r] = U[UREG + 4q + r][col]
    for (int idx = j; idx < UROWS * G4H; idx += 512) {
        int row = idx / G4H;        // 0..39
        int col = idx - row * G4H;
        Usf[(row >> 2) * 2048 + col * 4 + (row & 3)] = U[(UREG + row) * G4H + col];
    }

    // tokens for rows b0, b0+1
    const int is64 = g_tok64;
    for (int idx = j; idx < 2 * Tv; idx += 512) {
        int r = idx >> 9;
        int t = idx & (Tv - 1);
        int tok;
        if (is64) tok = (int)((const long long*)tokens)[(size_t)(b0 + r) * Tv + t];
        else      tok =       ((const int*)tokens)      [(size_t)(b0 + r) * Tv + t];
        tokb[idx] = tok;
    }
    if (j < 128) { hbuf[j * 2] = 0.0f; hbuf[j * 2 + 1] = 0.0f; }
    __syncthreads();

    const int cbase = dir * G4H;
    float c0 = 0.0f, c1 = 0.0f, hl0 = 0.0f, hl1 = 0.0f;

    int t0 = dir ? (Tv - 1) : 0;
    float xw0 = g_embW[(size_t)tokb[t0] * NW + cbase + j];
    float xw1 = g_embW[(size_t)tokb[Tv + t0] * NW + cbase + j];

    const ulonglong2* hb2 = (const ulonglong2*)hbuf;  // [k/2]: (pair k, pair k+1)

    for (int s = 0; s < Tv; ++s) {
        const int tc = dir ? (Tv - 1 - s) : s;

        // prefetch next step's input projection rows (hidden behind FMA loop)
        float nx0 = 0.0f, nx1 = 0.0f;
        if (s + 1 < Tv) {
            int tn = dir ? (tc - 1) : (tc + 1);
            nx0 = g_embW[(size_t)tokb[tn] * NW + cbase + j];
            nx1 = g_embW[(size_t)tokb[Tv + tn] * NW + cbase + j];
        }

        unsigned long long acc = pack2(xw0, xw1);   // lanes = (row0, row1)

#pragma unroll
        for (int k = 0; k < UREG; k += 2) {
            ulonglong2 hv = hb2[k >> 1];            // (h[k]r0,h[k]r1),(h[k+1]..)
            acc = fma2(hv.x, dup2(Ur[k]),     acc);
            acc = fma2(hv.y, dup2(Ur[k + 1]), acc);
        }
#pragma unroll
        for (int q = 0; q < UQ; q++) {
            float4 uu = *(const float4*)&Usf[q * 2048 + j * 4];
            ulonglong2 hv0 = hb2[(UREG >> 1) + q * 2];
            ulonglong2 hv1 = hb2[(UREG >> 1) + q * 2 + 1];
            acc = fma2(hv0.x, dup2(uu.x), acc);
            acc = fma2(hv0.y, dup2(uu.y), acc);
            acc = fma2(hv1.x, dup2(uu.z), acc);
            acc = fma2(hv1.y, dup2(uu.w), acc);
        }

        float a0, a1;
        unpack2(acc, a0, a1);

        // activations: i,f,o -> sigmoid (j<256 or j>=384), g -> tanh
        float g0, g1;
        if ((j < 256) || (j >= 384)) { g0 = sigmoid_f(a0); g1 = sigmoid_f(a1); }
        else                         { g0 = tanh_f(a0);    g1 = tanh_f(a1);    }
        *(float2*)&zbuf[j * 2] = make_float2(g0, g1);
        __syncthreads();

        if (j < 128) {
            float i0 = zbuf[j * 2],           i1 = zbuf[j * 2 + 1];
            float f0 = zbuf[(j + 128) * 2],   f1 = zbuf[(j + 128) * 2 + 1];
            float gg0 = zbuf[(j + 256) * 2],  gg1 = zbuf[(j + 256) * 2 + 1];
            float o0 = zbuf[(j + 384) * 2],   o1 = zbuf[(j + 384) * 2 + 1];
            c0 = fmaf(f0, c0, i0 * gg0);
            c1 = fmaf(f1, c1, i1 * gg1);
            hl0 = o0 * tanh_f(c0);
            hl1 = o1 * tanh_f(c1);
            hbuf[j * 2]     = hl0;
            hbuf[j * 2 + 1] = hl1;
            out[((size_t)b0 * Tv + tc) * 256 + dir * 128 + j]       = hl0;
            out[((size_t)(b0 + 1) * Tv + tc) * 256 + dir * 128 + j] = hl1;
        }
        __syncthreads();
        xw0 = nx0;
        xw1 = nx1;
    }

    // final states: layout after out[B,T,2H]: h_fw, c_fw, h_bw, c_bw (each [B,H])
    if (j < 128) {
        size_t fin  = (size_t)Bv * Tv * 256;
        size_t hoff = fin + (size_t)(dir * 2) * (Bv * Hv);
        out[hoff + (size_t)b0 * Hv + j]                 = hl0;
        out[hoff + (size_t)(b0 + 1) * Hv + j]           = hl1;
        out[hoff + Bv * Hv + (size_t)b0 * Hv + j]       = c0;
        out[hoff + Bv * Hv + (size_t)(b0 + 1) * Hv + j] = c1;
    }
}

// ---------------------------------------------------------------------------
// Inputs (metadata order): tokens, emb, W_fw, U_fw, b_fw, W_bw, U_bw, b_bw
// Output: out[B,T,2H] fp32, then h_fw, c_fw, h_bw, c_bw (each [B,H])
// ---------------------------------------------------------------------------
extern "C" void kernel_launch(void* const* d_in, const int* in_sizes, int n_in,
                              void* d_out, int out_size)
{
    const void*  tokens = d_in[0];
    const float* emb = (const float*)d_in[1];
    const float* Wfw = (const float*)d_in[2];
    const float* Ufw = (const float*)d_in[3];
    const float* bfw = (const float*)d_in[4];
    const float* Wbw = (const float*)d_in[5];
    const float* Ubw = (const float*)d_in[6];
    const float* bbw = (const float*)d_in[7];
    float* out = (float*)d_out;

    (void)in_sizes; (void)n_in; (void)out_size;

    detect_tok_kernel<<<1, 256>>>((const unsigned int*)tokens);

    dim3 ggrid(Vv / 128, NW / 128);
    embw_gemm_kernel<<<ggrid, 256>>>(emb, Wfw, Wbw, bfw, bbw);

    cudaFuncSetAttribute(lstm_kernel,
                         cudaFuncAttributeMaxDynamicSharedMemorySize,
                         LSTM_SMEM_BYTES);
    lstm_kernel<<<128, 512, LSTM_SMEM_BYTES>>>(tokens, Ufw, Ubw, out);
}

// round 8
// speedup vs baseline: 1.0386x; 1.0011x over previous
#include <cuda_runtime.h>
#include <cstdint>
#include <cstddef>

// Problem constants
#define Bv   128
#define Tv   512
#define Vv   32000
#define Ev   256
#define Hv   128
#define G4H  512      // 4*H (gate columns per direction)
#define NW   1024     // 4H * 2 directions (concat fw|bw)

// Scratch: embW = emb @ [W_fw | W_bw] + [b_fw | b_bw]   (131 MB, device global)
__device__ float g_embW[(size_t)Vv * NW];
// tokens dtype flag: 1 if int64 layout, 0 if int32
__device__ int g_tok64;

// ---------------------------------------------------------------------------
// f32x2 packed-math helpers (sm_103a; ptxas never emits FFMA2 from C++)
// ---------------------------------------------------------------------------
__device__ __forceinline__ unsigned long long fma2(unsigned long long a,
                                                   unsigned long long b,
                                                   unsigned long long c) {
    unsigned long long d;
    asm("fma.rn.f32x2 %0, %1, %2, %3;" : "=l"(d) : "l"(a), "l"(b), "l"(c));
    return d;
}
__device__ __forceinline__ unsigned long long dup2(float x) {
    unsigned long long d;
    asm("mov.b64 %0, {%1, %1};" : "=l"(d) : "f"(x));
    return d;
}
__device__ __forceinline__ unsigned long long pack2(float lo, float hi) {
    unsigned long long d;
    asm("mov.b64 %0, {%1, %2};" : "=l"(d) : "f"(lo), "f"(hi));
    return d;
}
__device__ __forceinline__ void unpack2(unsigned long long v, float& lo, float& hi) {
    asm("mov.b64 {%0, %1}, %2;" : "=f"(lo), "=f"(hi) : "l"(v));
}

// ---------------------------------------------------------------------------
// Kernel 0: detect tokens dtype. If int64, every odd 32-bit word (high half)
// is 0 (tokens < 32000). If int32, odd words are random tokens (~0 zeros).
// ---------------------------------------------------------------------------
__global__ void detect_tok_kernel(const unsigned int* __restrict__ w) {
    __shared__ int cnt;
    if (threadIdx.x == 0) cnt = 0;
    __syncthreads();
    int local = 0;
    for (int i = threadIdx.x; i < (Bv * Tv / 2); i += blockDim.x)
        if (w[2 * i + 1] == 0u) local++;
    atomicAdd(&cnt, local);
    __syncthreads();
    if (threadIdx.x == 0) g_tok64 = (cnt > (Bv * Tv / 4)) ? 1 : 0;
}

// ---------------------------------------------------------------------------
// Kernel 1: embW[v][n] = sum_k emb[v][k] * W[k][n] + bias[n]
// M=32000, K=256, N=1024. 128x128 tile, BK=8, 256 threads, 8x8 per thread.
// Inner product in packed f32x2: 32 FFMA2 + 8 ALU packs per kk (was 64 FFMA).
// ---------------------------------------------------------------------------
__global__ __launch_bounds__(256) void embw_gemm_kernel(
    const float* __restrict__ emb,
    const float* __restrict__ Wfw, const float* __restrict__ Wbw,
    const float* __restrict__ bfw, const float* __restrict__ bbw)
{
    __shared__ float As[8][128];
    __shared__ float Bs[8][128];

    const int tid = threadIdx.x;
    const int m0 = blockIdx.x * 128;
    const int n0 = blockIdx.y * 128;

    const float* Wp;
    const float* bp;
    int nb;
    if (n0 < G4H) { Wp = Wfw; bp = bfw; nb = n0; }
    else          { Wp = Wbw; bp = bbw; nb = n0 - G4H; }

    const int ar = tid >> 1;          // A row within tile (0..127)
    const int ac = (tid & 1) * 4;     // A col group (0 or 4)
    const int br = tid >> 5;          // B row within k-tile (0..7)
    const int bc = (tid & 31) * 4;    // B col group
    const int tx = tid & 15;
    const int ty = tid >> 4;

    unsigned long long acc[8][4];     // acc[i][j2] = packed (col 2*j2, 2*j2+1)
#pragma unroll
    for (int i = 0; i < 8; i++)
#pragma unroll
        for (int j2 = 0; j2 < 4; j2++) acc[i][j2] = 0ull;

    // prefetch first k-tile into registers
    float4 av = *(const float4*)&emb[(size_t)(m0 + ar) * Ev + ac];
    float4 bv = *(const float4*)&Wp[(size_t)br * G4H + nb + bc];

    for (int kt = 0; kt < Ev / 8; ++kt) {
        As[ac + 0][ar] = av.x; As[ac + 1][ar] = av.y;
        As[ac + 2][ar] = av.z; As[ac + 3][ar] = av.w;
        *(float4*)&Bs[br][bc] = bv;
        __syncthreads();
        if (kt + 1 < Ev / 8) {
            int k0 = (kt + 1) * 8;
            av = *(const float4*)&emb[(size_t)(m0 + ar) * Ev + k0 + ac];
            bv = *(const float4*)&Wp[(size_t)(k0 + br) * G4H + nb + bc];
        }
#pragma unroll
        for (int kk = 0; kk < 8; ++kk) {
            float a[8];
            *(float4*)&a[0] = *(const float4*)&As[kk][ty * 8];
            *(float4*)&a[4] = *(const float4*)&As[kk][ty * 8 + 4];
            ulonglong2 b0 = *(const ulonglong2*)&Bs[kk][tx * 8];
            ulonglong2 b1 = *(const ulonglong2*)&Bs[kk][tx * 8 + 4];
#pragma unroll
            for (int i = 0; i < 8; i++) {
                unsigned long long ad = dup2(a[i]);
                acc[i][0] = fma2(ad, b0.x, acc[i][0]);
                acc[i][1] = fma2(ad, b0.y, acc[i][1]);
                acc[i][2] = fma2(ad, b1.x, acc[i][2]);
                acc[i][3] = fma2(ad, b1.y, acc[i][3]);
            }
        }
        __syncthreads();
    }

    // epilogue: unpack, add bias, store
    float bias[8];
    *(float4*)&bias[0] = *(const float4*)&bp[nb + tx * 8];
    *(float4*)&bias[4] = *(const float4*)&bp[nb + tx * 8 + 4];
#pragma unroll
    for (int i = 0; i < 8; i++) {
        int row = m0 + ty * 8 + i;
        float c[8];
#pragma unroll
        for (int j2 = 0; j2 < 4; j2++)
            unpack2(acc[i][j2], c[2 * j2], c[2 * j2 + 1]);
        float4 v0, v1;
        v0.x = c[0] + bias[0]; v0.y = c[1] + bias[1];
        v0.z = c[2] + bias[2]; v0.w = c[3] + bias[3];
        v1.x = c[4] + bias[4]; v1.y = c[5] + bias[5];
        v1.z = c[6] + bias[6]; v1.w = c[7] + bias[7];
        *(float4*)&g_embW[(size_t)row * NW + n0 + tx * 8]     = v0;
        *(float4*)&g_embW[(size_t)row * NW + n0 + tx * 8 + 4] = v1;
    }
}

// ---------------------------------------------------------------------------
// Kernel 2: persistent LSTM recurrence, packed-f32x2 across the 2 batch rows.
// grid = 128 blocks: blockIdx.x&1 = direction, >>1 = batch group (2 rows).
// 512 threads: thread j owns z-column j. Accumulator = f32x2 (row0, row1).
// U[:,j]: k<88 in registers (dup-packed at use, ALU pipe), k>=88 in SMEM
// (40 rows, 80 KB). h broadcast from SMEM as ulonglong2 (naturally paired).
// ---------------------------------------------------------------------------
__device__ __forceinline__ float sigmoid_f(float x) {
    return 1.0f / (1.0f + __expf(-x));
}
__device__ __forceinline__ float tanh_f(float x) {
    float e = __expf(-2.0f * fabsf(x));
    float t = (1.0f - e) / (1.0f + e);
    return copysignf(t, x);
}

#define UREG   88                       // U k-rows held in registers
#define UROWS  (Hv - UREG)              // 40 rows in smem
#define UQ     (UROWS / 4)              // 10 float4 groups per thread
#define LSTM_SMEM_BYTES ((UROWS * G4H + 1024 + 256 + 1024) * 4)

__global__ __launch_bounds__(512, 1) void lstm_kernel(
    const void*  __restrict__ tokens,
    const float* __restrict__ Ufw,
    const float* __restrict__ Ubw,
    float* __restrict__ out)
{
    extern __shared__ float smem[];
    float* Usf  = smem;                     // [UQ][512][4] u quads, rows 88..127
    float* zbuf = smem + UROWS * G4H;       // [512][2] activated gates
    float* hbuf = zbuf + 1024;              // [128][2] hidden state (interleaved)
    int*   tokb = (int*)(hbuf + 256);       // [2][512] tokens for this block

    const int j   = threadIdx.x;
    const int dir = blockIdx.x & 1;
    const int grp = blockIdx.x >> 1;
    const int b0  = grp * 2;
    const float* U = dir ? Ubw : Ufw;

    // U[k][j] for k in [0,UREG) -> registers
    float Ur[UREG];
#pragma unroll
    for (int k = 0; k < UREG; k++) Ur[k] = U[k * G4H + j];

    // U rows UREG..127 -> SMEM as per-thread float4 quads:
    // Usf[q*2048 + col*4 + r] = U[UREG + 4q + r][col]
    for (int idx = j; idx < UROWS * G4H; idx += 512) {
        int row = idx / G4H;        // 0..39
        int col = idx - row * G4H;
        Usf[(row >> 2) * 2048 + col * 4 + (row & 3)] = U[(UREG + row) * G4H + col];
    }

    // tokens for rows b0, b0+1
    const int is64 = g_tok64;
    for (int idx = j; idx < 2 * Tv; idx += 512) {
        int r = idx >> 9;
        int t = idx & (Tv - 1);
        int tok;
        if (is64) tok = (int)((const long long*)tokens)[(size_t)(b0 + r) * Tv + t];
        else      tok =       ((const int*)tokens)      [(size_t)(b0 + r) * Tv + t];
        tokb[idx] = tok;
    }
    if (j < 128) { hbuf[j * 2] = 0.0f; hbuf[j * 2 + 1] = 0.0f; }
    __syncthreads();

    const int cbase = dir * G4H;
    float c0 = 0.0f, c1 = 0.0f, hl0 = 0.0f, hl1 = 0.0f;

    int t0 = dir ? (Tv - 1) : 0;
    float xw0 = g_embW[(size_t)tokb[t0] * NW + cbase + j];
    float xw1 = g_embW[(size_t)tokb[Tv + t0] * NW + cbase + j];

    const ulonglong2* hb2 = (const ulonglong2*)hbuf;  // [k/2]: (pair k, pair k+1)

    for (int s = 0; s < Tv; ++s) {
        const int tc = dir ? (Tv - 1 - s) : s;

        // prefetch next step's input projection rows (hidden behind FMA loop)
        float nx0 = 0.0f, nx1 = 0.0f;
        if (s + 1 < Tv) {
            int tn = dir ? (tc - 1) : (tc + 1);
            nx0 = g_embW[(size_t)tokb[tn] * NW + cbase + j];
            nx1 = g_embW[(size_t)tokb[Tv + tn] * NW + cbase + j];
        }

        unsigned long long acc = pack2(xw0, xw1);   // lanes = (row0, row1)

#pragma unroll
        for (int k = 0; k < UREG; k += 2) {
            ulonglong2 hv = hb2[k >> 1];            // (h[k]r0,h[k]r1),(h[k+1]..)
            acc = fma2(hv.x, dup2(Ur[k]),     acc);
            acc = fma2(hv.y, dup2(Ur[k + 1]), acc);
        }
#pragma unroll
        for (int q = 0; q < UQ; q++) {
            float4 uu = *(const float4*)&Usf[q * 2048 + j * 4];
            ulonglong2 hv0 = hb2[(UREG >> 1) + q * 2];
            ulonglong2 hv1 = hb2[(UREG >> 1) + q * 2 + 1];
            acc = fma2(hv0.x, dup2(uu.x), acc);
            acc = fma2(hv0.y, dup2(uu.y), acc);
            acc = fma2(hv1.x, dup2(uu.z), acc);
            acc = fma2(hv1.y, dup2(uu.w), acc);
        }

        float a0, a1;
        unpack2(acc, a0, a1);

        // activations: i,f,o -> sigmoid (j<256 or j>=384), g -> tanh
        float g0, g1;
        if ((j < 256) || (j >= 384)) { g0 = sigmoid_f(a0); g1 = sigmoid_f(a1); }
        else                         { g0 = tanh_f(a0);    g1 = tanh_f(a1);    }
        *(float2*)&zbuf[j * 2] = make_float2(g0, g1);
        __syncthreads();

        if (j < 128) {
            float i0 = zbuf[j * 2],           i1 = zbuf[j * 2 + 1];
            float f0 = zbuf[(j + 128) * 2],   f1 = zbuf[(j + 128) * 2 + 1];
            float gg0 = zbuf[(j + 256) * 2],  gg1 = zbuf[(j + 256) * 2 + 1];
            float o0 = zbuf[(j + 384) * 2],   o1 = zbuf[(j + 384) * 2 + 1];
            c0 = fmaf(f0, c0, i0 * gg0);
            c1 = fmaf(f1, c1, i1 * gg1);
            hl0 = o0 * tanh_f(c0);
            hl1 = o1 * tanh_f(c1);
            hbuf[j * 2]     = hl0;
            hbuf[j * 2 + 1] = hl1;
            out[((size_t)b0 * Tv + tc) * 256 + dir * 128 + j]       = hl0;
            out[((size_t)(b0 + 1) * Tv + tc) * 256 + dir * 128 + j] = hl1;
        }
        __syncthreads();
        xw0 = nx0;
        xw1 = nx1;
    }

    // final states: layout after out[B,T,2H]: h_fw, c_fw, h_bw, c_bw (each [B,H])
    if (j < 128) {
        size_t fin  = (size_t)Bv * Tv * 256;
        size_t hoff = fin + (size_t)(dir * 2) * (Bv * Hv);
        out[hoff + (size_t)b0 * Hv + j]                 = hl0;
        out[hoff + (size_t)(b0 + 1) * Hv + j]           = hl1;
        out[hoff + Bv * Hv + (size_t)b0 * Hv + j]       = c0;
        out[hoff + Bv * Hv + (size_t)(b0 + 1) * Hv + j] = c1;
    }
}

// ---------------------------------------------------------------------------
// Inputs (metadata order): tokens, emb, W_fw, U_fw, b_fw, W_bw, U_bw, b_bw
// Output: out[B,T,2H] fp32, then h_fw, c_fw, h_bw, c_bw (each [B,H])
// ---------------------------------------------------------------------------
extern "C" void kernel_launch(void* const* d_in, const int* in_sizes, int n_in,
                              void* d_out, int out_size)
{
    const void*  tokens = d_in[0];
    const float* emb = (const float*)d_in[1];
    const float* Wfw = (const float*)d_in[2];
    const float* Ufw = (const float*)d_in[3];
    const float* bfw = (const float*)d_in[4];
    const float* Wbw = (const float*)d_in[5];
    const float* Ubw = (const float*)d_in[6];
    const float* bbw = (const float*)d_in[7];
    float* out = (float*)d_out;

    (void)in_sizes; (void)n_in; (void)out_size;

    detect_tok_kernel<<<1, 256>>>((const unsigned int*)tokens);

    dim3 ggrid(Vv / 128, NW / 128);
    embw_gemm_kernel<<<ggrid, 256>>>(emb, Wfw, Wbw, bfw, bbw);

    cudaFuncSetAttribute(lstm_kernel,
                         cudaFuncAttributeMaxDynamicSharedMemorySize,
                         LSTM_SMEM_BYTES);
    lstm_kernel<<<128, 512, LSTM_SMEM_BYTES>>>(tokens, Ufw, Ubw, out);
}

// round 9
// speedup vs baseline: 1.0388x; 1.0002x over previous
#include <cuda_runtime.h>
#include <cstdint>
#include <cstddef>

// Problem constants
#define Bv   128
#define Tv   512
#define Vv   32000
#define Ev   256
#define Hv   128
#define G4H  512      // 4*H (gate columns per direction)
#define NW   1024     // 4H * 2 directions (concat fw|bw)

// Scratch: embW = emb @ [W_fw | W_bw] + [b_fw | b_bw]   (131 MB, device global)
__device__ float g_embW[(size_t)Vv * NW];
// tokens dtype flag: 1 if int64 layout, 0 if int32
__device__ int g_tok64;

// ---------------------------------------------------------------------------
// f32x2 packed-math helpers (sm_103a; ptxas never emits FFMA2 from C++)
// ---------------------------------------------------------------------------
__device__ __forceinline__ unsigned long long fma2(unsigned long long a,
                                                   unsigned long long b,
                                                   unsigned long long c) {
    unsigned long long d;
    asm("fma.rn.f32x2 %0, %1, %2, %3;" : "=l"(d) : "l"(a), "l"(b), "l"(c));
    return d;
}
__device__ __forceinline__ unsigned long long dup2(float x) {
    unsigned long long d;
    asm("mov.b64 %0, {%1, %1};" : "=l"(d) : "f"(x));
    return d;
}
__device__ __forceinline__ unsigned long long pack2(float lo, float hi) {
    unsigned long long d;
    asm("mov.b64 %0, {%1, %2};" : "=l"(d) : "f"(lo), "f"(hi));
    return d;
}
__device__ __forceinline__ void unpack2(unsigned long long v, float& lo, float& hi) {
    asm("mov.b64 {%0, %1}, %2;" : "=f"(lo), "=f"(hi) : "l"(v));
}

// ---------------------------------------------------------------------------
// Kernel 0: detect tokens dtype. If int64, every odd 32-bit word (high half)
// is 0 (tokens < 32000). If int32, odd words are random tokens (~0 zeros).
// ---------------------------------------------------------------------------
__global__ void detect_tok_kernel(const unsigned int* __restrict__ w) {
    __shared__ int cnt;
    if (threadIdx.x == 0) cnt = 0;
    __syncthreads();
    int local = 0;
    for (int i = threadIdx.x; i < (Bv * Tv / 2); i += blockDim.x)
        if (w[2 * i + 1] == 0u) local++;
    atomicAdd(&cnt, local);
    __syncthreads();
    if (threadIdx.x == 0) g_tok64 = (cnt > (Bv * Tv / 4)) ? 1 : 0;
}

// ---------------------------------------------------------------------------
// Kernel 1: embW[v][n] = sum_k emb[v][k] * W[k][n] + bias[n]
// M=32000, K=256, N=1024. 128x128 tile, BK=8, 256 threads, 8x8 per thread.
// Inner product in packed f32x2: 32 FFMA2 + 8 ALU packs per kk (was 64 FFMA).
// ---------------------------------------------------------------------------
__global__ __launch_bounds__(256) void embw_gemm_kernel(
    const float* __restrict__ emb,
    const float* __restrict__ Wfw, const float* __restrict__ Wbw,
    const float* __restrict__ bfw, const float* __restrict__ bbw)
{
    __shared__ float As[8][128];
    __shared__ float Bs[8][128];

    const int tid = threadIdx.x;
    const int m0 = blockIdx.x * 128;
    const int n0 = blockIdx.y * 128;

    const float* Wp;
    const float* bp;
    int nb;
    if (n0 < G4H) { Wp = Wfw; bp = bfw; nb = n0; }
    else          { Wp = Wbw; bp = bbw; nb = n0 - G4H; }

    const int ar = tid >> 1;          // A row within tile (0..127)
    const int ac = (tid & 1) * 4;     // A col group (0 or 4)
    const int br = tid >> 5;          // B row within k-tile (0..7)
    const int bc = (tid & 31) * 4;    // B col group
    const int tx = tid & 15;
    const int ty = tid >> 4;

    unsigned long long acc[8][4];     // acc[i][j2] = packed (col 2*j2, 2*j2+1)
#pragma unroll
    for (int i = 0; i < 8; i++)
#pragma unroll
        for (int j2 = 0; j2 < 4; j2++) acc[i][j2] = 0ull;

    // prefetch first k-tile into registers
    float4 av = *(const float4*)&emb[(size_t)(m0 + ar) * Ev + ac];
    float4 bv = *(const float4*)&Wp[(size_t)br * G4H + nb + bc];

    for (int kt = 0; kt < Ev / 8; ++kt) {
        As[ac + 0][ar] = av.x; As[ac + 1][ar] = av.y;
        As[ac + 2][ar] = av.z; As[ac + 3][ar] = av.w;
        *(float4*)&Bs[br][bc] = bv;
        __syncthreads();
        if (kt + 1 < Ev / 8) {
            int k0 = (kt + 1) * 8;
            av = *(const float4*)&emb[(size_t)(m0 + ar) * Ev + k0 + ac];
            bv = *(const float4*)&Wp[(size_t)(k0 + br) * G4H + nb + bc];
        }
#pragma unroll
        for (int kk = 0; kk < 8; ++kk) {
            float a[8];
            *(float4*)&a[0] = *(const float4*)&As[kk][ty * 8];
            *(float4*)&a[4] = *(const float4*)&As[kk][ty * 8 + 4];
            ulonglong2 b0 = *(const ulonglong2*)&Bs[kk][tx * 8];
            ulonglong2 b1 = *(const ulonglong2*)&Bs[kk][tx * 8 + 4];
#pragma unroll
            for (int i = 0; i < 8; i++) {
                unsigned long long ad = dup2(a[i]);
                acc[i][0] = fma2(ad, b0.x, acc[i][0]);
                acc[i][1] = fma2(ad, b0.y, acc[i][1]);
                acc[i][2] = fma2(ad, b1.x, acc[i][2]);
                acc[i][3] = fma2(ad, b1.y, acc[i][3]);
            }
        }
        __syncthreads();
    }

    // epilogue: unpack, add bias, store
    float bias[8];
    *(float4*)&bias[0] = *(const float4*)&bp[nb + tx * 8];
    *(float4*)&bias[4] = *(const float4*)&bp[nb + tx * 8 + 4];
#pragma unroll
    for (int i = 0; i < 8; i++) {
        int row = m0 + ty * 8 + i;
        float c[8];
#pragma unroll
        for (int j2 = 0; j2 < 4; j2++)
            unpack2(acc[i][j2], c[2 * j2], c[2 * j2 + 1]);
        float4 v0, v1;
        v0.x = c[0] + bias[0]; v0.y = c[1] + bias[1];
        v0.z = c[2] + bias[2]; v0.w = c[3] + bias[3];
        v1.x = c[4] + bias[4]; v1.y = c[5] + bias[5];
        v1.z = c[6] + bias[6]; v1.w = c[7] + bias[7];
        *(float4*)&g_embW[(size_t)row * NW + n0 + tx * 8]     = v0;
        *(float4*)&g_embW[(size_t)row * NW + n0 + tx * 8 + 4] = v1;
    }
}

// ---------------------------------------------------------------------------
// Kernel 2: persistent LSTM recurrence, packed-f32x2 across the 2 batch rows.
// grid = 128 blocks: blockIdx.x&1 = direction, >>1 = batch group (2 rows).
// 512 threads: thread j owns z-column j. Accumulator = f32x2 (row0, row1).
// U[:,j]: k<88 in registers (dup-packed at use, ALU pipe), k>=88 in SMEM
// (40 rows, 80 KB). h broadcast from SMEM as ulonglong2 (naturally paired).
// ---------------------------------------------------------------------------
__device__ __forceinline__ float sigmoid_f(float x) {
    return 1.0f / (1.0f + __expf(-x));
}
__device__ __forceinline__ float tanh_f(float x) {
    float e = __expf(-2.0f * fabsf(x));
    float t = (1.0f - e) / (1.0f + e);
    return copysignf(t, x);
}

#define UREG   88                       // U k-rows held in registers
#define UROWS  (Hv - UREG)              // 40 rows in smem
#define UQ     (UROWS / 4)              // 10 float4 groups per thread
#define LSTM_SMEM_BYTES ((UROWS * G4H + 1024 + 256 + 1024) * 4)

__global__ __launch_bounds__(512, 1) void lstm_kernel(
    const void*  __restrict__ tokens,
    const float* __restrict__ Ufw,
    const float* __restrict__ Ubw,
    float* __restrict__ out)
{
    extern __shared__ float smem[];
    float* Usf  = smem;                     // [UQ][512][4] u quads, rows 88..127
    float* zbuf = smem + UROWS * G4H;       // [512][2] activated gates
    float* hbuf = zbuf + 1024;              // [128][2] hidden state (interleaved)
    int*   tokb = (int*)(hbuf + 256);       // [2][512] tokens for this block

    const int j   = threadIdx.x;
    const int dir = blockIdx.x & 1;
    const int grp = blockIdx.x >> 1;
    const int b0  = grp * 2;
    const float* U = dir ? Ubw : Ufw;

    // U[k][j] for k in [0,UREG) -> registers
    float Ur[UREG];
#pragma unroll
    for (int k = 0; k < UREG; k++) Ur[k] = U[k * G4H + j];

    // U rows UREG..127 -> SMEM as per-thread float4 quads:
    // Usf[q*2048 + col*4 + r] = U[UREG + 4q + r][col]
    for (int idx = j; idx < UROWS * G4H; idx += 512) {
        int row = idx / G4H;        // 0..39
        int col = idx - row * G4H;
        Usf[(row >> 2) * 2048 + col * 4 + (row & 3)] = U[(UREG + row) * G4H + col];
    }

    // tokens for rows b0, b0+1
    const int is64 = g_tok64;
    for (int idx = j; idx < 2 * Tv; idx += 512) {
        int r = idx >> 9;
        int t = idx & (Tv - 1);
        int tok;
        if (is64) tok = (int)((const long long*)tokens)[(size_t)(b0 + r) * Tv + t];
        else      tok =       ((const int*)tokens)      [(size_t)(b0 + r) * Tv + t];
        tokb[idx] = tok;
    }
    if (j < 128) { hbuf[j * 2] = 0.0f; hbuf[j * 2 + 1] = 0.0f; }
    __syncthreads();

    const int cbase = dir * G4H;
    float c0 = 0.0f, c1 = 0.0f, hl0 = 0.0f, hl1 = 0.0f;

    int t0 = dir ? (Tv - 1) : 0;
    float xw0 = g_embW[(size_t)tokb[t0] * NW + cbase + j];
    float xw1 = g_embW[(size_t)tokb[Tv + t0] * NW + cbase + j];

    const ulonglong2* hb2 = (const ulonglong2*)hbuf;  // [k/2]: (pair k, pair k+1)

    for (int s = 0; s < Tv; ++s) {
        const int tc = dir ? (Tv - 1 - s) : s;

        // prefetch next step's input projection rows (hidden behind FMA loop)
        float nx0 = 0.0f, nx1 = 0.0f;
        if (s + 1 < Tv) {
            int tn = dir ? (tc - 1) : (tc + 1);
            nx0 = g_embW[(size_t)tokb[tn] * NW + cbase + j];
            nx1 = g_embW[(size_t)tokb[Tv + tn] * NW + cbase + j];
        }

        unsigned long long acc = pack2(xw0, xw1);   // lanes = (row0, row1)

#pragma unroll
        for (int k = 0; k < UREG; k += 2) {
            ulonglong2 hv = hb2[k >> 1];            // (h[k]r0,h[k]r1),(h[k+1]..)
            acc = fma2(hv.x, dup2(Ur[k]),     acc);
            acc = fma2(hv.y, dup2(Ur[k + 1]), acc);
        }
#pragma unroll
        for (int q = 0; q < UQ; q++) {
            float4 uu = *(const float4*)&Usf[q * 2048 + j * 4];
            ulonglong2 hv0 = hb2[(UREG >> 1) + q * 2];
            ulonglong2 hv1 = hb2[(UREG >> 1) + q * 2 + 1];
            acc = fma2(hv0.x, dup2(uu.x), acc);
            acc = fma2(hv0.y, dup2(uu.y), acc);
            acc = fma2(hv1.x, dup2(uu.z), acc);
            acc = fma2(hv1.y, dup2(uu.w), acc);
        }

        float a0, a1;
        unpack2(acc, a0, a1);

        // activations: i,f,o -> sigmoid (j<256 or j>=384), g -> tanh
        float g0, g1;
        if ((j < 256) || (j >= 384)) { g0 = sigmoid_f(a0); g1 = sigmoid_f(a1); }
        else                         { g0 = tanh_f(a0);    g1 = tanh_f(a1);    }
        *(float2*)&zbuf[j * 2] = make_float2(g0, g1);
        __syncthreads();

        if (j < 128) {
            float i0 = zbuf[j * 2],           i1 = zbuf[j * 2 + 1];
            float f0 = zbuf[(j + 128) * 2],   f1 = zbuf[(j + 128) * 2 + 1];
            float gg0 = zbuf[(j + 256) * 2],  gg1 = zbuf[(j + 256) * 2 + 1];
            float o0 = zbuf[(j + 384) * 2],   o1 = zbuf[(j + 384) * 2 + 1];
            c0 = fmaf(f0, c0, i0 * gg0);
            c1 = fmaf(f1, c1, i1 * gg1);
            hl0 = o0 * tanh_f(c0);
            hl1 = o1 * tanh_f(c1);
            hbuf[j * 2]     = hl0;
            hbuf[j * 2 + 1] = hl1;
            out[((size_t)b0 * Tv + tc) * 256 + dir * 128 + j]       = hl0;
            out[((size_t)(b0 + 1) * Tv + tc) * 256 + dir * 128 + j] = hl1;
        }
        __syncthreads();
        xw0 = nx0;
        xw1 = nx1;
    }

    // final states: layout after out[B,T,2H]: h_fw, c_fw, h_bw, c_bw (each [B,H])
    if (j < 128) {
        size_t fin  = (size_t)Bv * Tv * 256;
        size_t hoff = fin + (size_t)(dir * 2) * (Bv * Hv);
        out[hoff + (size_t)b0 * Hv + j]                 = hl0;
        out[hoff + (size_t)(b0 + 1) * Hv + j]           = hl1;
        out[hoff + Bv * Hv + (size_t)b0 * Hv + j]       = c0;
        out[hoff + Bv * Hv + (size_t)(b0 + 1) * Hv + j] = c1;
    }
}

// ---------------------------------------------------------------------------
// Inputs (metadata order): tokens, emb, W_fw, U_fw, b_fw, W_bw, U_bw, b_bw
// Output: out[B,T,2H] fp32, then h_fw, c_fw, h_bw, c_bw (each [B,H])
// ---------------------------------------------------------------------------
extern "C" void kernel_launch(void* const* d_in, const int* in_sizes, int n_in,
                              void* d_out, int out_size)
{
    const void*  tokens = d_in[0];
    const float* emb = (const float*)d_in[1];
    const float* Wfw = (const float*)d_in[2];
    const float* Ufw = (const float*)d_in[3];
    const float* bfw = (const float*)d_in[4];
    const float* Wbw = (const float*)d_in[5];
    const float* Ubw = (const float*)d_in[6];
    const float* bbw = (const float*)d_in[7];
    float* out = (float*)d_out;

    (void)in_sizes; (void)n_in; (void)out_size;

    detect_tok_kernel<<<1, 256>>>((const unsigned int*)tokens);

    dim3 ggrid(Vv / 128, NW / 128);
    embw_gemm_kernel<<<ggrid, 256>>>(emb, Wfw, Wbw, bfw, bbw);

    cudaFuncSetAttribute(lstm_kernel,
                         cudaFuncAttributeMaxDynamicSharedMemorySize,
                         LSTM_SMEM_BYTES);
    lstm_kernel<<<128, 512, LSTM_SMEM_BYTES>>>(tokens, Ufw, Ubw, out);
}

// round 10
// speedup vs baseline: 1.2174x; 1.1719x over previous
#include <cuda_runtime.h>
#include <cstdint>
#include <cstddef>

// Problem constants
#define Bv   128
#define Tv   512
#define Vv   32000
#define Ev   256
#define Hv   128
#define G4H  512      // 4*H (gate columns per direction)
#define NW   1024     // 4H * 2 directions (concat fw|bw)

// Scratch: embW = emb @ [W_fw | W_bw] + [b_fw | b_bw]   (131 MB, device global)
__device__ float g_embW[(size_t)Vv * NW];

// ---------------------------------------------------------------------------
// f32x2 packed-math helpers (sm_103a; ptxas never emits FFMA2 from C++)
// ---------------------------------------------------------------------------
__device__ __forceinline__ unsigned long long fma2(unsigned long long a,
                                                   unsigned long long b,
                                                   unsigned long long c) {
    unsigned long long d;
    asm("fma.rn.f32x2 %0, %1, %2, %3;" : "=l"(d) : "l"(a), "l"(b), "l"(c));
    return d;
}
__device__ __forceinline__ unsigned long long dup2(float x) {
    unsigned long long d;
    asm("mov.b64 %0, {%1, %1};" : "=l"(d) : "f"(x));
    return d;
}
__device__ __forceinline__ unsigned long long pack2(float lo, float hi) {
    unsigned long long d;
    asm("mov.b64 %0, {%1, %2};" : "=l"(d) : "f"(lo), "f"(hi));
    return d;
}
__device__ __forceinline__ void unpack2(unsigned long long v, float& lo, float& hi) {
    asm("mov.b64 {%0, %1}, %2;" : "=f"(lo), "=f"(hi) : "l"(v));
}

// ---------------------------------------------------------------------------
// Kernel 1: embW[v][n] = sum_k emb[v][k] * W[k][n] + bias[n]
// M=32000, K=256, N=1024. 128x128 tile, BK=8, 256 threads, 8x8 per thread.
// Packed f32x2 inner product (fma-pipe-bound; ALU dup cost = half of fma).
// ---------------------------------------------------------------------------
__global__ __launch_bounds__(256) void embw_gemm_kernel(
    const float* __restrict__ emb,
    const float* __restrict__ Wfw, const float* __restrict__ Wbw,
    const float* __restrict__ bfw, const float* __restrict__ bbw)
{
    __shared__ float As[8][128];
    __shared__ float Bs[8][128];

    const int tid = threadIdx.x;
    const int m0 = blockIdx.x * 128;
    const int n0 = blockIdx.y * 128;

    const float* Wp;
    const float* bp;
    int nb;
    if (n0 < G4H) { Wp = Wfw; bp = bfw; nb = n0; }
    else          { Wp = Wbw; bp = bbw; nb = n0 - G4H; }

    const int ar = tid >> 1;          // A row within tile (0..127)
    const int ac = (tid & 1) * 4;     // A col group (0 or 4)
    const int br = tid >> 5;          // B row within k-tile (0..7)
    const int bc = (tid & 31) * 4;    // B col group
    const int tx = tid & 15;
    const int ty = tid >> 4;

    unsigned long long acc[8][4];     // acc[i][j2] = packed (col 2*j2, 2*j2+1)
#pragma unroll
    for (int i = 0; i < 8; i++)
#pragma unroll
        for (int j2 = 0; j2 < 4; j2++) acc[i][j2] = 0ull;

    // prefetch first k-tile into registers
    float4 av = *(const float4*)&emb[(size_t)(m0 + ar) * Ev + ac];
    float4 bv = *(const float4*)&Wp[(size_t)br * G4H + nb + bc];

    for (int kt = 0; kt < Ev / 8; ++kt) {
        As[ac + 0][ar] = av.x; As[ac + 1][ar] = av.y;
        As[ac + 2][ar] = av.z; As[ac + 3][ar] = av.w;
        *(float4*)&Bs[br][bc] = bv;
        __syncthreads();
        if (kt + 1 < Ev / 8) {
            int k0 = (kt + 1) * 8;
            av = *(const float4*)&emb[(size_t)(m0 + ar) * Ev + k0 + ac];
            bv = *(const float4*)&Wp[(size_t)(k0 + br) * G4H + nb + bc];
        }
#pragma unroll
        for (int kk = 0; kk < 8; ++kk) {
            float a[8];
            *(float4*)&a[0] = *(const float4*)&As[kk][ty * 8];
            *(float4*)&a[4] = *(const float4*)&As[kk][ty * 8 + 4];
            ulonglong2 b0 = *(const ulonglong2*)&Bs[kk][tx * 8];
            ulonglong2 b1 = *(const ulonglong2*)&Bs[kk][tx * 8 + 4];
#pragma unroll
            for (int i = 0; i < 8; i++) {
                unsigned long long ad = dup2(a[i]);
                acc[i][0] = fma2(ad, b0.x, acc[i][0]);
                acc[i][1] = fma2(ad, b0.y, acc[i][1]);
                acc[i][2] = fma2(ad, b1.x, acc[i][2]);
                acc[i][3] = fma2(ad, b1.y, acc[i][3]);
            }
        }
        __syncthreads();
    }

    // epilogue: unpack, add bias, store
    float bias[8];
    *(float4*)&bias[0] = *(const float4*)&bp[nb + tx * 8];
    *(float4*)&bias[4] = *(const float4*)&bp[nb + tx * 8 + 4];
#pragma unroll
    for (int i = 0; i < 8; i++) {
        int row = m0 + ty * 8 + i;
        float c[8];
#pragma unroll
        for (int j2 = 0; j2 < 4; j2++)
            unpack2(acc[i][j2], c[2 * j2], c[2 * j2 + 1]);
        float4 v0, v1;
        v0.x = c[0] + bias[0]; v0.y = c[1] + bias[1];
        v0.z = c[2] + bias[2]; v0.w = c[3] + bias[3];
        v1.x = c[4] + bias[4]; v1.y = c[5] + bias[5];
        v1.z = c[6] + bias[6]; v1.w = c[7] + bias[7];
        *(float4*)&g_embW[(size_t)row * NW + n0 + tx * 8]     = v0;
        *(float4*)&g_embW[(size_t)row * NW + n0 + tx * 8 + 4] = v1;
    }
}

// ---------------------------------------------------------------------------
// Kernel 2: persistent LSTM recurrence, f32x2 lanes = (even-k, odd-k) partials.
// grid = 128 blocks (1/SM): blockIdx.x&1 = direction, >>1 = batch pair.
// 256 threads: thread t owns cols {t, t+256} for BOTH batch rows.
// U packed once at init: pairs (U[2p][j],U[2p+1][j]) -> 44 u64 regs per col
// (k rows 0..87) + 10 smem quads per col (k rows 88..127). Zero inner-loop ALU.
// h kept planar per row; broadcast LDS.128 gives 2 packed h-pairs per load.
// ---------------------------------------------------------------------------
__device__ __forceinline__ float sigmoid_f(float x) {
    return 1.0f / (1.0f + __expf(-x));
}
__device__ __forceinline__ float tanh_f(float x) {
    float e = __expf(-2.0f * fabsf(x));
    float t = (1.0f - e) / (1.0f + e);
    return copysignf(t, x);
}

#define NPR   44                        // register k-pairs per col (k 0..87)
#define NQS   10                        // smem quads (k 88..127)
// smem: Uq[10][512] float4 + hrow[2][128] f32 + zb[512] float2 + tokb[2][512] int
#define LSTM_SMEM_BYTES (NQS * G4H * 16 + 256 * 4 + 512 * 8 + 1024 * 4)

__global__ __launch_bounds__(256, 1) void lstm_kernel(
    const void*  __restrict__ tokens,
    const float* __restrict__ Ufw,
    const float* __restrict__ Ubw,
    float* __restrict__ out)
{
    extern __shared__ float smem[];
    float4* Uq   = (float4*)smem;                       // [NQS][512]
    float*  hrow = (float*)(Uq + NQS * G4H);            // [2][128] planar
    float2* zb   = (float2*)(hrow + 256);               // [512] (row0,row1)
    int*    tokb = (int*)(zb + 512);                    // [2][512]
    __shared__ int s_cnt;

    const int t   = threadIdx.x;
    const int dir = blockIdx.x & 1;
    const int b0  = (blockIdx.x >> 1) * 2;
    const int j0  = t;
    const int j1  = t + 256;
    const float* U = dir ? Ubw : Ufw;

    // ---- inline tokens-dtype detection (first 8 KB, in-bounds either way) ----
    if (t == 0) s_cnt = 0;
    __syncthreads();
    {
        const unsigned int* w = (const unsigned int*)tokens;
        int local = 0;
        for (int i = t; i < 1024; i += 256)
            if (w[2 * i + 1] == 0u) local++;
        atomicAdd(&s_cnt, local);
    }
    __syncthreads();
    const int is64 = (s_cnt > 512);

    // ---- pack U k-pairs into registers (k rows 0..2*NPR-1) ----
    unsigned long long Ur0[NPR], Ur1[NPR];
#pragma unroll
    for (int p = 0; p < NPR; p++) {
        Ur0[p] = pack2(U[(2 * p) * G4H + j0], U[(2 * p + 1) * G4H + j0]);
        Ur1[p] = pack2(U[(2 * p) * G4H + j1], U[(2 * p + 1) * G4H + j1]);
    }

    // ---- remaining k rows (88..127) into smem quads: Uq[q][col] = U[88+4q..+3][col]
    for (int idx = t; idx < NQS * G4H; idx += 256) {
        int q = idx >> 9;
        int col = idx & 511;
        int k = 2 * NPR + 4 * q;
        float4 v;
        v.x = U[(k + 0) * G4H + col];
        v.y = U[(k + 1) * G4H + col];
        v.z = U[(k + 2) * G4H + col];
        v.w = U[(k + 3) * G4H + col];
        Uq[q * G4H + col] = v;
    }

    // ---- tokens for rows b0, b0+1 ----
    for (int idx = t; idx < 2 * Tv; idx += 256) {
        int r  = idx >> 9;
        int tt = idx & (Tv - 1);
        int tok;
        if (is64) tok = (int)((const long long*)tokens)[(size_t)(b0 + r) * Tv + tt];
        else      tok =       ((const int*)tokens)      [(size_t)(b0 + r) * Tv + tt];
        tokb[idx] = tok;
    }
    if (t < 128) { hrow[t] = 0.0f; hrow[128 + t] = 0.0f; }
    __syncthreads();

    const int cbase = dir * G4H;
    const float* eb = g_embW;
    float c0 = 0.0f, c1 = 0.0f, hl0 = 0.0f, hl1 = 0.0f;

    // initial xw prefetch: [col][row]
    int t0 = dir ? (Tv - 1) : 0;
    int tk0 = tokb[t0], tk1 = tokb[Tv + t0];
    float xw00 = eb[(size_t)tk0 * NW + cbase + j0];
    float xw01 = eb[(size_t)tk1 * NW + cbase + j0];
    float xw10 = eb[(size_t)tk0 * NW + cbase + j1];
    float xw11 = eb[(size_t)tk1 * NW + cbase + j1];

    const ulonglong2* h0q = (const ulonglong2*)hrow;          // row0 h, quads
    const ulonglong2* h1q = (const ulonglong2*)(hrow + 128);  // row1 h, quads
    const ulonglong2* Uqv = (const ulonglong2*)Uq;

    for (int s = 0; s < Tv; ++s) {
        const int tc = dir ? (Tv - 1 - s) : s;

        // prefetch next step's xw (hidden behind FMA loop)
        float nx00 = 0.0f, nx01 = 0.0f, nx10 = 0.0f, nx11 = 0.0f;
        if (s + 1 < Tv) {
            int tn = dir ? (tc - 1) : (tc + 1);
            int a = tokb[tn], b = tokb[Tv + tn];
            nx00 = eb[(size_t)a * NW + cbase + j0];
            nx01 = eb[(size_t)b * NW + cbase + j0];
            nx10 = eb[(size_t)a * NW + cbase + j1];
            nx11 = eb[(size_t)b * NW + cbase + j1];
        }

        // acc[col][row], lanes = (even-k partial, odd-k partial)
        unsigned long long a00 = pack2(xw00, 0.0f);
        unsigned long long a01 = pack2(xw01, 0.0f);
        unsigned long long a10 = pack2(xw10, 0.0f);
        unsigned long long a11 = pack2(xw11, 0.0f);

#pragma unroll
        for (int q = 0; q < NPR / 2; q++) {          // k = 4q .. 4q+3, reg U
            ulonglong2 h0 = h0q[q];
            ulonglong2 h1 = h1q[q];
            a00 = fma2(h0.x, Ur0[2 * q],     a00);
            a00 = fma2(h0.y, Ur0[2 * q + 1], a00);
            a01 = fma2(h1.x, Ur0[2 * q],     a01);
            a01 = fma2(h1.y, Ur0[2 * q + 1], a01);
            a10 = fma2(h0.x, Ur1[2 * q],     a10);
            a10 = fma2(h0.y, Ur1[2 * q + 1], a10);
            a11 = fma2(h1.x, Ur1[2 * q],     a11);
            a11 = fma2(h1.y, Ur1[2 * q + 1], a11);
        }
#pragma unroll
        for (int q = NPR / 2; q < 32; q++) {         // k = 4q .. 4q+3, smem U
            ulonglong2 h0 = h0q[q];
            ulonglong2 h1 = h1q[q];
            ulonglong2 ua = Uqv[(q - NPR / 2) * G4H + j0];
            ulonglong2 ub = Uqv[(q - NPR / 2) * G4H + j1];
            a00 = fma2(h0.x, ua.x, a00);
            a00 = fma2(h0.y, ua.y, a00);
            a01 = fma2(h1.x, ua.x, a01);
            a01 = fma2(h1.y, ua.y, a01);
            a10 = fma2(h0.x, ub.x, a10);
            a10 = fma2(h0.y, ub.y, a10);
            a11 = fma2(h1.x, ub.x, a11);
            a11 = fma2(h1.y, ub.y, a11);
        }

        float lo, hi;
        float z00, z01, z10, z11;
        unpack2(a00, lo, hi); z00 = lo + hi;
        unpack2(a01, lo, hi); z01 = lo + hi;
        unpack2(a10, lo, hi); z10 = lo + hi;
        unpack2(a11, lo, hi); z11 = lo + hi;

        // col j0 in [0,256): gates i/f -> sigmoid.
        // col j1 in [256,512): t<128 -> g (tanh), else o (sigmoid).
        float g00 = sigmoid_f(z00), g01 = sigmoid_f(z01);
        float g10, g11;
        if (t < 128) { g10 = tanh_f(z10);    g11 = tanh_f(z11);    }
        else         { g10 = sigmoid_f(z10); g11 = sigmoid_f(z11); }
        zb[j0] = make_float2(g00, g01);
        zb[j1] = make_float2(g10, g11);
        __syncthreads();

        if (t < 128) {
            float2 zi = zb[t];
            float2 zf = zb[t + 128];
            float2 zg = zb[t + 256];
            float2 zo = zb[t + 384];
            c0 = fmaf(zf.x, c0, zi.x * zg.x);
            c1 = fmaf(zf.y, c1, zi.y * zg.y);
            hl0 = zo.x * tanh_f(c0);
            hl1 = zo.y * tanh_f(c1);
            hrow[t]       = hl0;
            hrow[128 + t] = hl1;
            out[((size_t)b0 * Tv + tc) * 256 + dir * 128 + t]       = hl0;
            out[((size_t)(b0 + 1) * Tv + tc) * 256 + dir * 128 + t] = hl1;
        }
        __syncthreads();
        xw00 = nx00; xw01 = nx01; xw10 = nx10; xw11 = nx11;
    }

    // final states: after out[B,T,2H]: h_fw, c_fw, h_bw, c_bw (each [B,H])
    if (t < 128) {
        size_t fin  = (size_t)Bv * Tv * 256;
        size_t hoff = fin + (size_t)(dir * 2) * (Bv * Hv);
        out[hoff + (size_t)b0 * Hv + t]                 = hl0;
        out[hoff + (size_t)(b0 + 1) * Hv + t]           = hl1;
        out[hoff + Bv * Hv + (size_t)b0 * Hv + t]       = c0;
        out[hoff + Bv * Hv + (size_t)(b0 + 1) * Hv + t] = c1;
    }
}

// ---------------------------------------------------------------------------
// Inputs (metadata order): tokens, emb, W_fw, U_fw, b_fw, W_bw, U_bw, b_bw
// Output: out[B,T,2H] fp32, then h_fw, c_fw, h_bw, c_bw (each [B,H])
// ---------------------------------------------------------------------------
extern "C" void kernel_launch(void* const* d_in, const int* in_sizes, int n_in,
                              void* d_out, int out_size)
{
    const void*  tokens = d_in[0];
    const float* emb = (const float*)d_in[1];
    const float* Wfw = (const float*)d_in[2];
    const float* Ufw = (const float*)d_in[3];
    const float* bfw = (const float*)d_in[4];
    const float* Wbw = (const float*)d_in[5];
    const float* Ubw = (const float*)d_in[6];
    const float* bbw = (const float*)d_in[7];
    float* out = (float*)d_out;

    (void)in_sizes; (void)n_in; (void)out_size;

    dim3 ggrid(Vv / 128, NW / 128);
    embw_gemm_kernel<<<ggrid, 256>>>(emb, Wfw, Wbw, bfw, bbw);

    cudaFuncSetAttribute(lstm_kernel,
                         cudaFuncAttributeMaxDynamicSharedMemorySize,
                         LSTM_SMEM_BYTES);
    lstm_kernel<<<128, 256, LSTM_SMEM_BYTES>>>(tokens, Ufw, Ubw, out);
}

// round 11
// speedup vs baseline: 1.2189x; 1.0012x over previous
#include <cuda_runtime.h>
#include <cstdint>
#include <cstddef>

// Problem constants
#define Bv   128
#define Tv   512
#define Vv   32000
#define Ev   256
#define Hv   128
#define G4H  512      // 4*H (gate columns per direction)
#define NW   1024     // 4H * 2 directions (concat fw|bw)

// Scratch: embW = emb @ [W_fw | W_bw] + [b_fw | b_bw]   (131 MB, device global)
__device__ float g_embW[(size_t)Vv * NW];

// ---------------------------------------------------------------------------
// f32x2 packed-math helpers (sm_103a; ptxas never emits FFMA2 from C++)
// ---------------------------------------------------------------------------
__device__ __forceinline__ unsigned long long fma2(unsigned long long a,
                                                   unsigned long long b,
                                                   unsigned long long c) {
    unsigned long long d;
    asm("fma.rn.f32x2 %0, %1, %2, %3;" : "=l"(d) : "l"(a), "l"(b), "l"(c));
    return d;
}
__device__ __forceinline__ unsigned long long dup2(float x) {
    unsigned long long d;
    asm("mov.b64 %0, {%1, %1};" : "=l"(d) : "f"(x));
    return d;
}
__device__ __forceinline__ unsigned long long pack2(float lo, float hi) {
    unsigned long long d;
    asm("mov.b64 %0, {%1, %2};" : "=l"(d) : "f"(lo), "f"(hi));
    return d;
}
__device__ __forceinline__ void unpack2(unsigned long long v, float& lo, float& hi) {
    asm("mov.b64 {%0, %1}, %2;" : "=f"(lo), "=f"(hi) : "l"(v));
}

// ---------------------------------------------------------------------------
// Kernel 1: embW[v][n] = sum_k emb[v][k] * W[k][n] + bias[n]
// M=32000, K=256, N=1024. 128x128 tile, BK=8, 256 threads, 8x8 per thread.
// Packed f32x2 inner product (fma-pipe-bound; ALU dup cost = half of fma).
// ---------------------------------------------------------------------------
__global__ __launch_bounds__(256) void embw_gemm_kernel(
    const float* __restrict__ emb,
    const float* __restrict__ Wfw, const float* __restrict__ Wbw,
    const float* __restrict__ bfw, const float* __restrict__ bbw)
{
    __shared__ float As[8][128];
    __shared__ float Bs[8][128];

    const int tid = threadIdx.x;
    const int m0 = blockIdx.x * 128;
    const int n0 = blockIdx.y * 128;

    const float* Wp;
    const float* bp;
    int nb;
    if (n0 < G4H) { Wp = Wfw; bp = bfw; nb = n0; }
    else          { Wp = Wbw; bp = bbw; nb = n0 - G4H; }

    const int ar = tid >> 1;          // A row within tile (0..127)
    const int ac = (tid & 1) * 4;     // A col group (0 or 4)
    const int br = tid >> 5;          // B row within k-tile (0..7)
    const int bc = (tid & 31) * 4;    // B col group
    const int tx = tid & 15;
    const int ty = tid >> 4;

    unsigned long long acc[8][4];     // acc[i][j2] = packed (col 2*j2, 2*j2+1)
#pragma unroll
    for (int i = 0; i < 8; i++)
#pragma unroll
        for (int j2 = 0; j2 < 4; j2++) acc[i][j2] = 0ull;

    // prefetch first k-tile into registers
    float4 av = *(const float4*)&emb[(size_t)(m0 + ar) * Ev + ac];
    float4 bv = *(const float4*)&Wp[(size_t)br * G4H + nb + bc];

    for (int kt = 0; kt < Ev / 8; ++kt) {
        As[ac + 0][ar] = av.x; As[ac + 1][ar] = av.y;
        As[ac + 2][ar] = av.z; As[ac + 3][ar] = av.w;
        *(float4*)&Bs[br][bc] = bv;
        __syncthreads();
        if (kt + 1 < Ev / 8) {
            int k0 = (kt + 1) * 8;
            av = *(const float4*)&emb[(size_t)(m0 + ar) * Ev + k0 + ac];
            bv = *(const float4*)&Wp[(size_t)(k0 + br) * G4H + nb + bc];
        }
#pragma unroll
        for (int kk = 0; kk < 8; ++kk) {
            float a[8];
            *(float4*)&a[0] = *(const float4*)&As[kk][ty * 8];
            *(float4*)&a[4] = *(const float4*)&As[kk][ty * 8 + 4];
            ulonglong2 b0 = *(const ulonglong2*)&Bs[kk][tx * 8];
            ulonglong2 b1 = *(const ulonglong2*)&Bs[kk][tx * 8 + 4];
#pragma unroll
            for (int i = 0; i < 8; i++) {
                unsigned long long ad = dup2(a[i]);
                acc[i][0] = fma2(ad, b0.x, acc[i][0]);
                acc[i][1] = fma2(ad, b0.y, acc[i][1]);
                acc[i][2] = fma2(ad, b1.x, acc[i][2]);
                acc[i][3] = fma2(ad, b1.y, acc[i][3]);
            }
        }
        __syncthreads();
    }

    // epilogue: unpack, add bias, store
    float bias[8];
    *(float4*)&bias[0] = *(const float4*)&bp[nb + tx * 8];
    *(float4*)&bias[4] = *(const float4*)&bp[nb + tx * 8 + 4];
#pragma unroll
    for (int i = 0; i < 8; i++) {
        int row = m0 + ty * 8 + i;
        float c[8];
#pragma unroll
        for (int j2 = 0; j2 < 4; j2++)
            unpack2(acc[i][j2], c[2 * j2], c[2 * j2 + 1]);
        float4 v0, v1;
        v0.x = c[0] + bias[0]; v0.y = c[1] + bias[1];
        v0.z = c[2] + bias[2]; v0.w = c[3] + bias[3];
        v1.x = c[4] + bias[4]; v1.y = c[5] + bias[5];
        v1.z = c[6] + bias[6]; v1.w = c[7] + bias[7];
        *(float4*)&g_embW[(size_t)row * NW + n0 + tx * 8]     = v0;
        *(float4*)&g_embW[(size_t)row * NW + n0 + tx * 8 + 4] = v1;
    }
}

// ---------------------------------------------------------------------------
// Kernel 2: persistent LSTM recurrence, f32x2 lanes = (even-k, odd-k) partials.
// grid = 128 blocks (1/SM): blockIdx.x&1 = direction, >>1 = batch pair.
// 256 threads: thread t owns cols {t, t+256} for BOTH batch rows.
// U packed once at init: pairs (U[2p][j],U[2p+1][j]) -> 44 u64 regs per col
// (k rows 0..87) + 10 smem quads per col (k rows 88..127). Zero inner-loop ALU.
// h kept planar per row; broadcast LDS.128 gives 2 packed h-pairs per load.
// ---------------------------------------------------------------------------
__device__ __forceinline__ float sigmoid_f(float x) {
    return 1.0f / (1.0f + __expf(-x));
}
__device__ __forceinline__ float tanh_f(float x) {
    float e = __expf(-2.0f * fabsf(x));
    float t = (1.0f - e) / (1.0f + e);
    return copysignf(t, x);
}

#define NPR   44                        // register k-pairs per col (k 0..87)
#define NQS   10                        // smem quads (k 88..127)
// smem: Uq[10][512] float4 + hrow[2][128] f32 + zb[512] float2 + tokb[2][512] int
#define LSTM_SMEM_BYTES (NQS * G4H * 16 + 256 * 4 + 512 * 8 + 1024 * 4)

__global__ __launch_bounds__(256, 1) void lstm_kernel(
    const void*  __restrict__ tokens,
    const float* __restrict__ Ufw,
    const float* __restrict__ Ubw,
    float* __restrict__ out)
{
    extern __shared__ float smem[];
    float4* Uq   = (float4*)smem;                       // [NQS][512]
    float*  hrow = (float*)(Uq + NQS * G4H);            // [2][128] planar
    float2* zb   = (float2*)(hrow + 256);               // [512] (row0,row1)
    int*    tokb = (int*)(zb + 512);                    // [2][512]
    __shared__ int s_cnt;

    const int t   = threadIdx.x;
    const int dir = blockIdx.x & 1;
    const int b0  = (blockIdx.x >> 1) * 2;
    const int j0  = t;
    const int j1  = t + 256;
    const float* U = dir ? Ubw : Ufw;

    // ---- inline tokens-dtype detection (first 8 KB, in-bounds either way) ----
    if (t == 0) s_cnt = 0;
    __syncthreads();
    {
        const unsigned int* w = (const unsigned int*)tokens;
        int local = 0;
        for (int i = t; i < 1024; i += 256)
            if (w[2 * i + 1] == 0u) local++;
        atomicAdd(&s_cnt, local);
    }
    __syncthreads();
    const int is64 = (s_cnt > 512);

    // ---- pack U k-pairs into registers (k rows 0..2*NPR-1) ----
    unsigned long long Ur0[NPR], Ur1[NPR];
#pragma unroll
    for (int p = 0; p < NPR; p++) {
        Ur0[p] = pack2(U[(2 * p) * G4H + j0], U[(2 * p + 1) * G4H + j0]);
        Ur1[p] = pack2(U[(2 * p) * G4H + j1], U[(2 * p + 1) * G4H + j1]);
    }

    // ---- remaining k rows (88..127) into smem quads: Uq[q][col] = U[88+4q..+3][col]
    for (int idx = t; idx < NQS * G4H; idx += 256) {
        int q = idx >> 9;
        int col = idx & 511;
        int k = 2 * NPR + 4 * q;
        float4 v;
        v.x = U[(k + 0) * G4H + col];
        v.y = U[(k + 1) * G4H + col];
        v.z = U[(k + 2) * G4H + col];
        v.w = U[(k + 3) * G4H + col];
        Uq[q * G4H + col] = v;
    }

    // ---- tokens for rows b0, b0+1 ----
    for (int idx = t; idx < 2 * Tv; idx += 256) {
        int r  = idx >> 9;
        int tt = idx & (Tv - 1);
        int tok;
        if (is64) tok = (int)((const long long*)tokens)[(size_t)(b0 + r) * Tv + tt];
        else      tok =       ((const int*)tokens)      [(size_t)(b0 + r) * Tv + tt];
        tokb[idx] = tok;
    }
    if (t < 128) { hrow[t] = 0.0f; hrow[128 + t] = 0.0f; }
    __syncthreads();

    const int cbase = dir * G4H;
    const float* eb = g_embW;
    float c0 = 0.0f, c1 = 0.0f, hl0 = 0.0f, hl1 = 0.0f;

    // initial xw prefetch: [col][row]
    int t0 = dir ? (Tv - 1) : 0;
    int tk0 = tokb[t0], tk1 = tokb[Tv + t0];
    float xw00 = eb[(size_t)tk0 * NW + cbase + j0];
    float xw01 = eb[(size_t)tk1 * NW + cbase + j0];
    float xw10 = eb[(size_t)tk0 * NW + cbase + j1];
    float xw11 = eb[(size_t)tk1 * NW + cbase + j1];

    const ulonglong2* h0q = (const ulonglong2*)hrow;          // row0 h, quads
    const ulonglong2* h1q = (const ulonglong2*)(hrow + 128);  // row1 h, quads
    const ulonglong2* Uqv = (const ulonglong2*)Uq;

    for (int s = 0; s < Tv; ++s) {
        const int tc = dir ? (Tv - 1 - s) : s;

        // prefetch next step's xw (hidden behind FMA loop)
        float nx00 = 0.0f, nx01 = 0.0f, nx10 = 0.0f, nx11 = 0.0f;
        if (s + 1 < Tv) {
            int tn = dir ? (tc - 1) : (tc + 1);
            int a = tokb[tn], b = tokb[Tv + tn];
            nx00 = eb[(size_t)a * NW + cbase + j0];
            nx01 = eb[(size_t)b * NW + cbase + j0];
            nx10 = eb[(size_t)a * NW + cbase + j1];
            nx11 = eb[(size_t)b * NW + cbase + j1];
        }

        // acc[col][row], lanes = (even-k partial, odd-k partial)
        unsigned long long a00 = pack2(xw00, 0.0f);
        unsigned long long a01 = pack2(xw01, 0.0f);
        unsigned long long a10 = pack2(xw10, 0.0f);
        unsigned long long a11 = pack2(xw11, 0.0f);

#pragma unroll
        for (int q = 0; q < NPR / 2; q++) {          // k = 4q .. 4q+3, reg U
            ulonglong2 h0 = h0q[q];
            ulonglong2 h1 = h1q[q];
            a00 = fma2(h0.x, Ur0[2 * q],     a00);
            a00 = fma2(h0.y, Ur0[2 * q + 1], a00);
            a01 = fma2(h1.x, Ur0[2 * q],     a01);
            a01 = fma2(h1.y, Ur0[2 * q + 1], a01);
            a10 = fma2(h0.x, Ur1[2 * q],     a10);
            a10 = fma2(h0.y, Ur1[2 * q + 1], a10);
            a11 = fma2(h1.x, Ur1[2 * q],     a11);
            a11 = fma2(h1.y, Ur1[2 * q + 1], a11);
        }
#pragma unroll
        for (int q = NPR / 2; q < 32; q++) {         // k = 4q .. 4q+3, smem U
            ulonglong2 h0 = h0q[q];
            ulonglong2 h1 = h1q[q];
            ulonglong2 ua = Uqv[(q - NPR / 2) * G4H + j0];
            ulonglong2 ub = Uqv[(q - NPR / 2) * G4H + j1];
            a00 = fma2(h0.x, ua.x, a00);
            a00 = fma2(h0.y, ua.y, a00);
            a01 = fma2(h1.x, ua.x, a01);
            a01 = fma2(h1.y, ua.y, a01);
            a10 = fma2(h0.x, ub.x, a10);
            a10 = fma2(h0.y, ub.y, a10);
            a11 = fma2(h1.x, ub.x, a11);
            a11 = fma2(h1.y, ub.y, a11);
        }

        float lo, hi;
        float z00, z01, z10, z11;
        unpack2(a00, lo, hi); z00 = lo + hi;
        unpack2(a01, lo, hi); z01 = lo + hi;
        unpack2(a10, lo, hi); z10 = lo + hi;
        unpack2(a11, lo, hi); z11 = lo + hi;

        // col j0 in [0,256): gates i/f -> sigmoid.
        // col j1 in [256,512): t<128 -> g (tanh), else o (sigmoid).
        float g00 = sigmoid_f(z00), g01 = sigmoid_f(z01);
        float g10, g11;
        if (t < 128) { g10 = tanh_f(z10);    g11 = tanh_f(z11);    }
        else         { g10 = sigmoid_f(z10); g11 = sigmoid_f(z11); }
        zb[j0] = make_float2(g00, g01);
        zb[j1] = make_float2(g10, g11);
        __syncthreads();

        if (t < 128) {
            float2 zi = zb[t];
            float2 zf = zb[t + 128];
            float2 zg = zb[t + 256];
            float2 zo = zb[t + 384];
            c0 = fmaf(zf.x, c0, zi.x * zg.x);
            c1 = fmaf(zf.y, c1, zi.y * zg.y);
            hl0 = zo.x * tanh_f(c0);
            hl1 = zo.y * tanh_f(c1);
            hrow[t]       = hl0;
            hrow[128 + t] = hl1;
            out[((size_t)b0 * Tv + tc) * 256 + dir * 128 + t]       = hl0;
            out[((size_t)(b0 + 1) * Tv + tc) * 256 + dir * 128 + t] = hl1;
        }
        __syncthreads();
        xw00 = nx00; xw01 = nx01; xw10 = nx10; xw11 = nx11;
    }

    // final states: after out[B,T,2H]: h_fw, c_fw, h_bw, c_bw (each [B,H])
    if (t < 128) {
        size_t fin  = (size_t)Bv * Tv * 256;
        size_t hoff = fin + (size_t)(dir * 2) * (Bv * Hv);
        out[hoff + (size_t)b0 * Hv + t]                 = hl0;
        out[hoff + (size_t)(b0 + 1) * Hv + t]           = hl1;
        out[hoff + Bv * Hv + (size_t)b0 * Hv + t]       = c0;
        out[hoff + Bv * Hv + (size_t)(b0 + 1) * Hv + t] = c1;
    }
}

// ---------------------------------------------------------------------------
// Inputs (metadata order): tokens, emb, W_fw, U_fw, b_fw, W_bw, U_bw, b_bw
// Output: out[B,T,2H] fp32, then h_fw, c_fw, h_bw, c_bw (each [B,H])
// ---------------------------------------------------------------------------
extern "C" void kernel_launch(void* const* d_in, const int* in_sizes, int n_in,
                              void* d_out, int out_size)
{
    const void*  tokens = d_in[0];
    const float* emb = (const float*)d_in[1];
    const float* Wfw = (const float*)d_in[2];
    const float* Ufw = (const float*)d_in[3];
    const float* bfw = (const float*)d_in[4];
    const float* Wbw = (const float*)d_in[5];
    const float* Ubw = (const float*)d_in[6];
    const float* bbw = (const float*)d_in[7];
    float* out = (float*)d_out;

    (void)in_sizes; (void)n_in; (void)out_size;

    dim3 ggrid(Vv / 128, NW / 128);
    embw_gemm_kernel<<<ggrid, 256>>>(emb, Wfw, Wbw, bfw, bbw);

    cudaFuncSetAttribute(lstm_kernel,
                         cudaFuncAttributeMaxDynamicSharedMemorySize,
                         LSTM_SMEM_BYTES);
    lstm_kernel<<<128, 256, LSTM_SMEM_BYTES>>>(tokens, Ufw, Ubw, out);
}

// round 12
// speedup vs baseline: 1.3030x; 1.0690x over previous
#include <cuda_runtime.h>
#include <cstdint>
#include <cstddef>

// Problem constants
#define Bv   128
#define Tv   512
#define Vv   32000
#define Ev   256
#define Hv   128
#define G4H  512      // 4*H (gate columns per direction)
#define NW   1024     // 4H * 2 directions (concat fw|bw)

// Scratch: embW = emb @ [W_fw | W_bw] + [b_fw | b_bw]   (131 MB, device global)
__device__ float g_embW[(size_t)Vv * NW];

// ---------------------------------------------------------------------------
// f32x2 packed-math helpers (sm_103a; ptxas never emits FFMA2 from C++)
// ---------------------------------------------------------------------------
__device__ __forceinline__ unsigned long long fma2(unsigned long long a,
                                                   unsigned long long b,
                                                   unsigned long long c) {
    unsigned long long d;
    asm("fma.rn.f32x2 %0, %1, %2, %3;" : "=l"(d) : "l"(a), "l"(b), "l"(c));
    return d;
}
__device__ __forceinline__ unsigned long long dup2(float x) {
    unsigned long long d;
    asm("mov.b64 %0, {%1, %1};" : "=l"(d) : "f"(x));
    return d;
}
__device__ __forceinline__ unsigned long long pack2(float lo, float hi) {
    unsigned long long d;
    asm("mov.b64 %0, {%1, %2};" : "=l"(d) : "f"(lo), "f"(hi));
    return d;
}
__device__ __forceinline__ void unpack2(unsigned long long v, float& lo, float& hi) {
    asm("mov.b64 {%0, %1}, %2;" : "=f"(lo), "=f"(hi) : "l"(v));
}

// MUFU-direct activations (no divides, ~2-ulp accurate)
__device__ __forceinline__ float ex2f(float x) {
    float y; asm("ex2.approx.f32 %0, %1;" : "=f"(y) : "f"(x)); return y;
}
__device__ __forceinline__ float rcpf(float x) {
    float y; asm("rcp.approx.f32 %0, %1;" : "=f"(y) : "f"(x)); return y;
}
#define LOG2E 1.4426950408889634f
__device__ __forceinline__ float sigmoid_f(float x) {
    return rcpf(1.0f + ex2f(-LOG2E * x));          // 1/(1+e^-x)
}
__device__ __forceinline__ float tanh_f(float x) {
    return fmaf(-2.0f, rcpf(1.0f + ex2f(2.0f * LOG2E * x)), 1.0f); // 1-2/(1+e^2x)
}

// ---------------------------------------------------------------------------
// Kernel 1: embW[v][n] = sum_k emb[v][k] * W[k][n] + bias[n]
// M=32000, K=256, N=1024. 128x128 tile, BK=8, 256 threads, 8x8 per thread.
// Packed f32x2 inner product (fma-pipe-bound; ALU dup cost = half of fma).
// ---------------------------------------------------------------------------
__global__ __launch_bounds__(256) void embw_gemm_kernel(
    const float* __restrict__ emb,
    const float* __restrict__ Wfw, const float* __restrict__ Wbw,
    const float* __restrict__ bfw, const float* __restrict__ bbw)
{
    __shared__ float As[8][128];
    __shared__ float Bs[8][128];

    const int tid = threadIdx.x;
    const int m0 = blockIdx.x * 128;
    const int n0 = blockIdx.y * 128;

    const float* Wp;
    const float* bp;
    int nb;
    if (n0 < G4H) { Wp = Wfw; bp = bfw; nb = n0; }
    else          { Wp = Wbw; bp = bbw; nb = n0 - G4H; }

    const int ar = tid >> 1;          // A row within tile (0..127)
    const int ac = (tid & 1) * 4;     // A col group (0 or 4)
    const int br = tid >> 5;          // B row within k-tile (0..7)
    const int bc = (tid & 31) * 4;    // B col group
    const int tx = tid & 15;
    const int ty = tid >> 4;

    unsigned long long acc[8][4];     // acc[i][j2] = packed (col 2*j2, 2*j2+1)
#pragma unroll
    for (int i = 0; i < 8; i++)
#pragma unroll
        for (int j2 = 0; j2 < 4; j2++) acc[i][j2] = 0ull;

    // prefetch first k-tile into registers
    float4 av = *(const float4*)&emb[(size_t)(m0 + ar) * Ev + ac];
    float4 bv = *(const float4*)&Wp[(size_t)br * G4H + nb + bc];

    for (int kt = 0; kt < Ev / 8; ++kt) {
        As[ac + 0][ar] = av.x; As[ac + 1][ar] = av.y;
        As[ac + 2][ar] = av.z; As[ac + 3][ar] = av.w;
        *(float4*)&Bs[br][bc] = bv;
        __syncthreads();
        if (kt + 1 < Ev / 8) {
            int k0 = (kt + 1) * 8;
            av = *(const float4*)&emb[(size_t)(m0 + ar) * Ev + k0 + ac];
            bv = *(const float4*)&Wp[(size_t)(k0 + br) * G4H + nb + bc];
        }
#pragma unroll
        for (int kk = 0; kk < 8; ++kk) {
            float a[8];
            *(float4*)&a[0] = *(const float4*)&As[kk][ty * 8];
            *(float4*)&a[4] = *(const float4*)&As[kk][ty * 8 + 4];
            ulonglong2 b0 = *(const ulonglong2*)&Bs[kk][tx * 8];
            ulonglong2 b1 = *(const ulonglong2*)&Bs[kk][tx * 8 + 4];
#pragma unroll
            for (int i = 0; i < 8; i++) {
                unsigned long long ad = dup2(a[i]);
                acc[i][0] = fma2(ad, b0.x, acc[i][0]);
                acc[i][1] = fma2(ad, b0.y, acc[i][1]);
                acc[i][2] = fma2(ad, b1.x, acc[i][2]);
                acc[i][3] = fma2(ad, b1.y, acc[i][3]);
            }
        }
        __syncthreads();
    }

    // epilogue: unpack, add bias, store
    float bias[8];
    *(float4*)&bias[0] = *(const float4*)&bp[nb + tx * 8];
    *(float4*)&bias[4] = *(const float4*)&bp[nb + tx * 8 + 4];
#pragma unroll
    for (int i = 0; i < 8; i++) {
        int row = m0 + ty * 8 + i;
        float c[8];
#pragma unroll
        for (int j2 = 0; j2 < 4; j2++)
            unpack2(acc[i][j2], c[2 * j2], c[2 * j2 + 1]);
        float4 v0, v1;
        v0.x = c[0] + bias[0]; v0.y = c[1] + bias[1];
        v0.z = c[2] + bias[2]; v0.w = c[3] + bias[3];
        v1.x = c[4] + bias[4]; v1.y = c[5] + bias[5];
        v1.z = c[6] + bias[6]; v1.w = c[7] + bias[7];
        *(float4*)&g_embW[(size_t)row * NW + n0 + tx * 8]     = v0;
        *(float4*)&g_embW[(size_t)row * NW + n0 + tx * 8 + 4] = v1;
    }
}

// ---------------------------------------------------------------------------
// Kernel 2: persistent LSTM recurrence, f32x2 lanes = (even-k, odd-k) partials.
// grid = 128 blocks (1/SM): blockIdx.x&1 = direction, >>1 = batch pair.
// 256 threads, thread t owns cols {t, t+256} for BOTH batch rows.
// Gate pairing: t<128 owns (i,g) of cell t -> writes only p=i*g to smem.
//               t>=128 owns (f,o) of cell t-128 -> keeps f,o in regs, carries c,
//               runs the short epilogue.
// U packed once at init: 44 k-pairs/col in u64 regs + 10 smem quads/col.
// ---------------------------------------------------------------------------
#define NPR   44                        // register k-pairs per col (k 0..87)
#define NQS   10                        // smem quads (k 88..127)
// smem: Uq[10][512] float4 + hrow[2][128] f32 + pbuf[128] float2 + tokb[2][512]
#define LSTM_SMEM_BYTES (NQS * G4H * 16 + 256 * 4 + 128 * 8 + 1024 * 4)

__global__ __launch_bounds__(256, 1) void lstm_kernel(
    const void*  __restrict__ tokens,
    const float* __restrict__ Ufw,
    const float* __restrict__ Ubw,
    float* __restrict__ out)
{
    extern __shared__ float smem[];
    float4* Uq   = (float4*)smem;                       // [NQS][512]
    float*  hrow = (float*)(Uq + NQS * G4H);            // [2][128] planar
    float2* pbuf = (float2*)(hrow + 256);               // [128] (p_r0, p_r1)
    int*    tokb = (int*)(pbuf + 128);                  // [2][512]
    __shared__ int s_cnt;

    const int t   = threadIdx.x;
    const int dir = blockIdx.x & 1;
    const int b0  = (blockIdx.x >> 1) * 2;
    const int j0  = t;
    const int j1  = t + 256;
    const float* U = dir ? Ubw : Ufw;

    // ---- inline tokens-dtype detection (first 8 KB, in-bounds either way) ----
    if (t == 0) s_cnt = 0;
    __syncthreads();
    {
        const unsigned int* w = (const unsigned int*)tokens;
        int local = 0;
        for (int i = t; i < 1024; i += 256)
            if (w[2 * i + 1] == 0u) local++;
        atomicAdd(&s_cnt, local);
    }
    __syncthreads();
    const int is64 = (s_cnt > 512);

    // ---- pack U k-pairs into registers (k rows 0..2*NPR-1) ----
    unsigned long long Ur0[NPR], Ur1[NPR];
#pragma unroll
    for (int p = 0; p < NPR; p++) {
        Ur0[p] = pack2(U[(2 * p) * G4H + j0], U[(2 * p + 1) * G4H + j0]);
        Ur1[p] = pack2(U[(2 * p) * G4H + j1], U[(2 * p + 1) * G4H + j1]);
    }

    // ---- remaining k rows (88..127) into smem quads: Uq[q][col] = U[88+4q..+3][col]
    for (int idx = t; idx < NQS * G4H; idx += 256) {
        int q = idx >> 9;
        int col = idx & 511;
        int k = 2 * NPR + 4 * q;
        float4 v;
        v.x = U[(k + 0) * G4H + col];
        v.y = U[(k + 1) * G4H + col];
        v.z = U[(k + 2) * G4H + col];
        v.w = U[(k + 3) * G4H + col];
        Uq[q * G4H + col] = v;
    }

    // ---- tokens for rows b0, b0+1 ----
    for (int idx = t; idx < 2 * Tv; idx += 256) {
        int r  = idx >> 9;
        int tt = idx & (Tv - 1);
        int tok;
        if (is64) tok = (int)((const long long*)tokens)[(size_t)(b0 + r) * Tv + tt];
        else      tok =       ((const int*)tokens)      [(size_t)(b0 + r) * Tv + tt];
        tokb[idx] = tok;
    }
    if (t < 128) { hrow[t] = 0.0f; hrow[128 + t] = 0.0f; }
    __syncthreads();

    const int cbase = dir * G4H;
    const float* eb = g_embW;
    const int cell = t - 128;           // valid for fo-threads (t >= 128)
    float c0 = 0.0f, c1 = 0.0f, hl0 = 0.0f, hl1 = 0.0f;

    // initial xw prefetch: [col][row]
    int t0 = dir ? (Tv - 1) : 0;
    int tk0 = tokb[t0], tk1 = tokb[Tv + t0];
    float xw00 = eb[(size_t)tk0 * NW + cbase + j0];
    float xw01 = eb[(size_t)tk1 * NW + cbase + j0];
    float xw10 = eb[(size_t)tk0 * NW + cbase + j1];
    float xw11 = eb[(size_t)tk1 * NW + cbase + j1];

    const ulonglong2* h0q = (const ulonglong2*)hrow;          // row0 h, quads
    const ulonglong2* h1q = (const ulonglong2*)(hrow + 128);  // row1 h, quads
    const ulonglong2* Uqv = (const ulonglong2*)Uq;

    for (int s = 0; s < Tv; ++s) {
        const int tc = dir ? (Tv - 1 - s) : s;

        // prefetch next step's xw (hidden behind FMA loop)
        float nx00 = 0.0f, nx01 = 0.0f, nx10 = 0.0f, nx11 = 0.0f;
        if (s + 1 < Tv) {
            int tn = dir ? (tc - 1) : (tc + 1);
            int a = tokb[tn], b = tokb[Tv + tn];
            nx00 = eb[(size_t)a * NW + cbase + j0];
            nx01 = eb[(size_t)b * NW + cbase + j0];
            nx10 = eb[(size_t)a * NW + cbase + j1];
            nx11 = eb[(size_t)b * NW + cbase + j1];
        }

        // acc[col][row], lanes = (even-k partial, odd-k partial)
        unsigned long long a00 = pack2(xw00, 0.0f);
        unsigned long long a01 = pack2(xw01, 0.0f);
        unsigned long long a10 = pack2(xw10, 0.0f);
        unsigned long long a11 = pack2(xw11, 0.0f);

#pragma unroll
        for (int q = 0; q < NPR / 2; q++) {          // k = 4q .. 4q+3, reg U
            ulonglong2 h0 = h0q[q];
            ulonglong2 h1 = h1q[q];
            a00 = fma2(h0.x, Ur0[2 * q],     a00);
            a00 = fma2(h0.y, Ur0[2 * q + 1], a00);
            a01 = fma2(h1.x, Ur0[2 * q],     a01);
            a01 = fma2(h1.y, Ur0[2 * q + 1], a01);
            a10 = fma2(h0.x, Ur1[2 * q],     a10);
            a10 = fma2(h0.y, Ur1[2 * q + 1], a10);
            a11 = fma2(h1.x, Ur1[2 * q],     a11);
            a11 = fma2(h1.y, Ur1[2 * q + 1], a11);
        }
#pragma unroll
        for (int q = NPR / 2; q < 32; q++) {         // k = 4q .. 4q+3, smem U
            ulonglong2 h0 = h0q[q];
            ulonglong2 h1 = h1q[q];
            ulonglong2 ua = Uqv[(q - NPR / 2) * G4H + j0];
            ulonglong2 ub = Uqv[(q - NPR / 2) * G4H + j1];
            a00 = fma2(h0.x, ua.x, a00);
            a00 = fma2(h0.y, ua.y, a00);
            a01 = fma2(h1.x, ua.x, a01);
            a01 = fma2(h1.y, ua.y, a01);
            a10 = fma2(h0.x, ub.x, a10);
            a10 = fma2(h0.y, ub.y, a10);
            a11 = fma2(h1.x, ub.x, a11);
            a11 = fma2(h1.y, ub.y, a11);
        }

        float lo, hi;
        float z00, z01, z10, z11;
        unpack2(a00, lo, hi); z00 = lo + hi;
        unpack2(a01, lo, hi); z01 = lo + hi;
        unpack2(a10, lo, hi); z10 = lo + hi;
        unpack2(a11, lo, hi); z11 = lo + hi;

        float f0 = 0.0f, f1 = 0.0f, o0 = 0.0f, o1 = 0.0f;
        if (t < 128) {
            // (i, g) of cell t: write only the product p = i*g
            float i0 = sigmoid_f(z00), i1 = sigmoid_f(z01);
            float g0 = tanh_f(z10),    g1 = tanh_f(z11);
            pbuf[t] = make_float2(i0 * g0, i1 * g1);
        } else {
            // (f, o) of cell t-128: keep in registers
            f0 = sigmoid_f(z00); f1 = sigmoid_f(z01);
            o0 = sigmoid_f(z10); o1 = sigmoid_f(z11);
        }
        __syncthreads();

        if (t >= 128) {
            float2 p = pbuf[cell];
            c0 = fmaf(f0, c0, p.x);
            c1 = fmaf(f1, c1, p.y);
            hl0 = o0 * tanh_f(c0);
            hl1 = o1 * tanh_f(c1);
            hrow[cell]       = hl0;
            hrow[128 + cell] = hl1;
            out[((size_t)b0 * Tv + tc) * 256 + dir * 128 + cell]       = hl0;
            out[((size_t)(b0 + 1) * Tv + tc) * 256 + dir * 128 + cell] = hl1;
        }
        __syncthreads();
        xw00 = nx00; xw01 = nx01; xw10 = nx10; xw11 = nx11;
    }

    // final states: after out[B,T,2H]: h_fw, c_fw, h_bw, c_bw (each [B,H])
    if (t >= 128) {
        size_t fin  = (size_t)Bv * Tv * 256;
        size_t hoff = fin + (size_t)(dir * 2) * (Bv * Hv);
        out[hoff + (size_t)b0 * Hv + cell]                 = hl0;
        out[hoff + (size_t)(b0 + 1) * Hv + cell]           = hl1;
        out[hoff + Bv * Hv + (size_t)b0 * Hv + cell]       = c0;
        out[hoff + Bv * Hv + (size_t)(b0 + 1) * Hv + cell] = c1;
    }
}

// ---------------------------------------------------------------------------
// Inputs (metadata order): tokens, emb, W_fw, U_fw, b_fw, W_bw, U_bw, b_bw
// Output: out[B,T,2H] fp32, then h_fw, c_fw, h_bw, c_bw (each [B,H])
// ---------------------------------------------------------------------------
extern "C" void kernel_launch(void* const* d_in, const int* in_sizes, int n_in,
                              void* d_out, int out_size)
{
    const void*  tokens = d_in[0];
    const float* emb = (const float*)d_in[1];
    const float* Wfw = (const float*)d_in[2];
    const float* Ufw = (const float*)d_in[3];
    const float* bfw = (const float*)d_in[4];
    const float* Wbw = (const float*)d_in[5];
    const float* Ubw = (const float*)d_in[6];
    const float* bbw = (const float*)d_in[7];
    float* out = (float*)d_out;

    (void)in_sizes; (void)n_in; (void)out_size;

    dim3 ggrid(Vv / 128, NW / 128);
    embw_gemm_kernel<<<ggrid, 256>>>(emb, Wfw, Wbw, bfw, bbw);

    cudaFuncSetAttribute(lstm_kernel,
                         cudaFuncAttributeMaxDynamicSharedMemorySize,
                         LSTM_SMEM_BYTES);
    lstm_kernel<<<128, 256, LSTM_SMEM_BYTES>>>(tokens, Ufw, Ubw, out);
}

// round 13
// speedup vs baseline: 1.3031x; 1.0000x over previous
#include <cuda_runtime.h>
#include <cstdint>
#include <cstddef>

// Problem constants
#define Bv   128
#define Tv   512
#define Vv   32000
#define Ev   256
#define Hv   128
#define G4H  512      // 4*H (gate columns per direction)
#define NW   1024     // 4H * 2 directions (concat fw|bw)

// Scratch: embW = emb @ [W_fw | W_bw] + [b_fw | b_bw]   (131 MB, device global)
__device__ float g_embW[(size_t)Vv * NW];

// ---------------------------------------------------------------------------
// f32x2 packed-math helpers (sm_103a; ptxas never emits FFMA2 from C++)
// ---------------------------------------------------------------------------
__device__ __forceinline__ unsigned long long fma2(unsigned long long a,
                                                   unsigned long long b,
                                                   unsigned long long c) {
    unsigned long long d;
    asm("fma.rn.f32x2 %0, %1, %2, %3;" : "=l"(d) : "l"(a), "l"(b), "l"(c));
    return d;
}
__device__ __forceinline__ unsigned long long dup2(float x) {
    unsigned long long d;
    asm("mov.b64 %0, {%1, %1};" : "=l"(d) : "f"(x));
    return d;
}
__device__ __forceinline__ unsigned long long pack2(float lo, float hi) {
    unsigned long long d;
    asm("mov.b64 %0, {%1, %2};" : "=l"(d) : "f"(lo), "f"(hi));
    return d;
}
__device__ __forceinline__ void unpack2(unsigned long long v, float& lo, float& hi) {
    asm("mov.b64 {%0, %1}, %2;" : "=f"(lo), "=f"(hi) : "l"(v));
}

// MUFU-direct activations (no divides, ~2-ulp accurate)
__device__ __forceinline__ float ex2f(float x) {
    float y; asm("ex2.approx.f32 %0, %1;" : "=f"(y) : "f"(x)); return y;
}
__device__ __forceinline__ float rcpf(float x) {
    float y; asm("rcp.approx.f32 %0, %1;" : "=f"(y) : "f"(x)); return y;
}
#define LOG2E 1.4426950408889634f
__device__ __forceinline__ float sigmoid_f(float x) {
    return rcpf(1.0f + ex2f(-LOG2E * x));          // 1/(1+e^-x)
}
__device__ __forceinline__ float tanh_f(float x) {
    return fmaf(-2.0f, rcpf(1.0f + ex2f(2.0f * LOG2E * x)), 1.0f); // 1-2/(1+e^2x)
}

// ---------------------------------------------------------------------------
// Kernel 1: embW[v][n] = sum_k emb[v][k] * W[k][n] + bias[n]
// M=32000, K=256, N=1024. 128x128 tile, BK=8, 256 threads, 8x8 per thread.
// Packed f32x2 inner product (fma-pipe-bound; ALU dup cost = half of fma).
// ---------------------------------------------------------------------------
__global__ __launch_bounds__(256) void embw_gemm_kernel(
    const float* __restrict__ emb,
    const float* __restrict__ Wfw, const float* __restrict__ Wbw,
    const float* __restrict__ bfw, const float* __restrict__ bbw)
{
    __shared__ float As[8][128];
    __shared__ float Bs[8][128];

    const int tid = threadIdx.x;
    const int m0 = blockIdx.x * 128;
    const int n0 = blockIdx.y * 128;

    const float* Wp;
    const float* bp;
    int nb;
    if (n0 < G4H) { Wp = Wfw; bp = bfw; nb = n0; }
    else          { Wp = Wbw; bp = bbw; nb = n0 - G4H; }

    const int ar = tid >> 1;          // A row within tile (0..127)
    const int ac = (tid & 1) * 4;     // A col group (0 or 4)
    const int br = tid >> 5;          // B row within k-tile (0..7)
    const int bc = (tid & 31) * 4;    // B col group
    const int tx = tid & 15;
    const int ty = tid >> 4;

    unsigned long long acc[8][4];     // acc[i][j2] = packed (col 2*j2, 2*j2+1)
#pragma unroll
    for (int i = 0; i < 8; i++)
#pragma unroll
        for (int j2 = 0; j2 < 4; j2++) acc[i][j2] = 0ull;

    // prefetch first k-tile into registers
    float4 av = *(const float4*)&emb[(size_t)(m0 + ar) * Ev + ac];
    float4 bv = *(const float4*)&Wp[(size_t)br * G4H + nb + bc];

    for (int kt = 0; kt < Ev / 8; ++kt) {
        As[ac + 0][ar] = av.x; As[ac + 1][ar] = av.y;
        As[ac + 2][ar] = av.z; As[ac + 3][ar] = av.w;
        *(float4*)&Bs[br][bc] = bv;
        __syncthreads();
        if (kt + 1 < Ev / 8) {
            int k0 = (kt + 1) * 8;
            av = *(const float4*)&emb[(size_t)(m0 + ar) * Ev + k0 + ac];
            bv = *(const float4*)&Wp[(size_t)(k0 + br) * G4H + nb + bc];
        }
#pragma unroll
        for (int kk = 0; kk < 8; ++kk) {
            float a[8];
            *(float4*)&a[0] = *(const float4*)&As[kk][ty * 8];
            *(float4*)&a[4] = *(const float4*)&As[kk][ty * 8 + 4];
            ulonglong2 b0 = *(const ulonglong2*)&Bs[kk][tx * 8];
            ulonglong2 b1 = *(const ulonglong2*)&Bs[kk][tx * 8 + 4];
#pragma unroll
            for (int i = 0; i < 8; i++) {
                unsigned long long ad = dup2(a[i]);
                acc[i][0] = fma2(ad, b0.x, acc[i][0]);
                acc[i][1] = fma2(ad, b0.y, acc[i][1]);
                acc[i][2] = fma2(ad, b1.x, acc[i][2]);
                acc[i][3] = fma2(ad, b1.y, acc[i][3]);
            }
        }
        __syncthreads();
    }

    // epilogue: unpack, add bias, store
    float bias[8];
    *(float4*)&bias[0] = *(const float4*)&bp[nb + tx * 8];
    *(float4*)&bias[4] = *(const float4*)&bp[nb + tx * 8 + 4];
#pragma unroll
    for (int i = 0; i < 8; i++) {
        int row = m0 + ty * 8 + i;
        float c[8];
#pragma unroll
        for (int j2 = 0; j2 < 4; j2++)
            unpack2(acc[i][j2], c[2 * j2], c[2 * j2 + 1]);
        float4 v0, v1;
        v0.x = c[0] + bias[0]; v0.y = c[1] + bias[1];
        v0.z = c[2] + bias[2]; v0.w = c[3] + bias[3];
        v1.x = c[4] + bias[4]; v1.y = c[5] + bias[5];
        v1.z = c[6] + bias[6]; v1.w = c[7] + bias[7];
        *(float4*)&g_embW[(size_t)row * NW + n0 + tx * 8]     = v0;
        *(float4*)&g_embW[(size_t)row * NW + n0 + tx * 8 + 4] = v1;
    }
}

// ---------------------------------------------------------------------------
// Kernel 2: persistent LSTM recurrence, f32x2 lanes = (even-k, odd-k) partials.
// grid = 128 blocks (1/SM): blockIdx.x&1 = direction, >>1 = batch pair.
// 256 threads, thread t owns cols {t, t+256} for BOTH batch rows.
// Gate pairing: t<128 owns (i,g) of cell t -> writes only p=i*g to smem.
//               t>=128 owns (f,o) of cell t-128 -> keeps f,o in regs, carries c,
//               runs the short epilogue.
// U packed once at init: 44 k-pairs/col in u64 regs + 10 smem quads/col.
// ---------------------------------------------------------------------------
#define NPR   44                        // register k-pairs per col (k 0..87)
#define NQS   10                        // smem quads (k 88..127)
// smem: Uq[10][512] float4 + hrow[2][128] f32 + pbuf[128] float2 + tokb[2][512]
#define LSTM_SMEM_BYTES (NQS * G4H * 16 + 256 * 4 + 128 * 8 + 1024 * 4)

__global__ __launch_bounds__(256, 1) void lstm_kernel(
    const void*  __restrict__ tokens,
    const float* __restrict__ Ufw,
    const float* __restrict__ Ubw,
    float* __restrict__ out)
{
    extern __shared__ float smem[];
    float4* Uq   = (float4*)smem;                       // [NQS][512]
    float*  hrow = (float*)(Uq + NQS * G4H);            // [2][128] planar
    float2* pbuf = (float2*)(hrow + 256);               // [128] (p_r0, p_r1)
    int*    tokb = (int*)(pbuf + 128);                  // [2][512]
    __shared__ int s_cnt;

    const int t   = threadIdx.x;
    const int dir = blockIdx.x & 1;
    const int b0  = (blockIdx.x >> 1) * 2;
    const int j0  = t;
    const int j1  = t + 256;
    const float* U = dir ? Ubw : Ufw;

    // ---- inline tokens-dtype detection (first 8 KB, in-bounds either way) ----
    if (t == 0) s_cnt = 0;
    __syncthreads();
    {
        const unsigned int* w = (const unsigned int*)tokens;
        int local = 0;
        for (int i = t; i < 1024; i += 256)
            if (w[2 * i + 1] == 0u) local++;
        atomicAdd(&s_cnt, local);
    }
    __syncthreads();
    const int is64 = (s_cnt > 512);

    // ---- pack U k-pairs into registers (k rows 0..2*NPR-1) ----
    unsigned long long Ur0[NPR], Ur1[NPR];
#pragma unroll
    for (int p = 0; p < NPR; p++) {
        Ur0[p] = pack2(U[(2 * p) * G4H + j0], U[(2 * p + 1) * G4H + j0]);
        Ur1[p] = pack2(U[(2 * p) * G4H + j1], U[(2 * p + 1) * G4H + j1]);
    }

    // ---- remaining k rows (88..127) into smem quads: Uq[q][col] = U[88+4q..+3][col]
    for (int idx = t; idx < NQS * G4H; idx += 256) {
        int q = idx >> 9;
        int col = idx & 511;
        int k = 2 * NPR + 4 * q;
        float4 v;
        v.x = U[(k + 0) * G4H + col];
        v.y = U[(k + 1) * G4H + col];
        v.z = U[(k + 2) * G4H + col];
        v.w = U[(k + 3) * G4H + col];
        Uq[q * G4H + col] = v;
    }

    // ---- tokens for rows b0, b0+1 ----
    for (int idx = t; idx < 2 * Tv; idx += 256) {
        int r  = idx >> 9;
        int tt = idx & (Tv - 1);
        int tok;
        if (is64) tok = (int)((const long long*)tokens)[(size_t)(b0 + r) * Tv + tt];
        else      tok =       ((const int*)tokens)      [(size_t)(b0 + r) * Tv + tt];
        tokb[idx] = tok;
    }
    if (t < 128) { hrow[t] = 0.0f; hrow[128 + t] = 0.0f; }
    __syncthreads();

    const int cbase = dir * G4H;
    const float* eb = g_embW;
    const int cell = t - 128;           // valid for fo-threads (t >= 128)
    float c0 = 0.0f, c1 = 0.0f, hl0 = 0.0f, hl1 = 0.0f;

    // initial xw prefetch: [col][row]
    int t0 = dir ? (Tv - 1) : 0;
    int tk0 = tokb[t0], tk1 = tokb[Tv + t0];
    float xw00 = eb[(size_t)tk0 * NW + cbase + j0];
    float xw01 = eb[(size_t)tk1 * NW + cbase + j0];
    float xw10 = eb[(size_t)tk0 * NW + cbase + j1];
    float xw11 = eb[(size_t)tk1 * NW + cbase + j1];

    const ulonglong2* h0q = (const ulonglong2*)hrow;          // row0 h, quads
    const ulonglong2* h1q = (const ulonglong2*)(hrow + 128);  // row1 h, quads
    const ulonglong2* Uqv = (const ulonglong2*)Uq;

    for (int s = 0; s < Tv; ++s) {
        const int tc = dir ? (Tv - 1 - s) : s;

        // prefetch next step's xw (hidden behind FMA loop)
        float nx00 = 0.0f, nx01 = 0.0f, nx10 = 0.0f, nx11 = 0.0f;
        if (s + 1 < Tv) {
            int tn = dir ? (tc - 1) : (tc + 1);
            int a = tokb[tn], b = tokb[Tv + tn];
            nx00 = eb[(size_t)a * NW + cbase + j0];
            nx01 = eb[(size_t)b * NW + cbase + j0];
            nx10 = eb[(size_t)a * NW + cbase + j1];
            nx11 = eb[(size_t)b * NW + cbase + j1];
        }

        // acc[col][row], lanes = (even-k partial, odd-k partial)
        unsigned long long a00 = pack2(xw00, 0.0f);
        unsigned long long a01 = pack2(xw01, 0.0f);
        unsigned long long a10 = pack2(xw10, 0.0f);
        unsigned long long a11 = pack2(xw11, 0.0f);

#pragma unroll
        for (int q = 0; q < NPR / 2; q++) {          // k = 4q .. 4q+3, reg U
            ulonglong2 h0 = h0q[q];
            ulonglong2 h1 = h1q[q];
            a00 = fma2(h0.x, Ur0[2 * q],     a00);
            a00 = fma2(h0.y, Ur0[2 * q + 1], a00);
            a01 = fma2(h1.x, Ur0[2 * q],     a01);
            a01 = fma2(h1.y, Ur0[2 * q + 1], a01);
            a10 = fma2(h0.x, Ur1[2 * q],     a10);
            a10 = fma2(h0.y, Ur1[2 * q + 1], a10);
            a11 = fma2(h1.x, Ur1[2 * q],     a11);
            a11 = fma2(h1.y, Ur1[2 * q + 1], a11);
        }
#pragma unroll
        for (int q = NPR / 2; q < 32; q++) {         // k = 4q .. 4q+3, smem U
            ulonglong2 h0 = h0q[q];
            ulonglong2 h1 = h1q[q];
            ulonglong2 ua = Uqv[(q - NPR / 2) * G4H + j0];
            ulonglong2 ub = Uqv[(q - NPR / 2) * G4H + j1];
            a00 = fma2(h0.x, ua.x, a00);
            a00 = fma2(h0.y, ua.y, a00);
            a01 = fma2(h1.x, ua.x, a01);
            a01 = fma2(h1.y, ua.y, a01);
            a10 = fma2(h0.x, ub.x, a10);
            a10 = fma2(h0.y, ub.y, a10);
            a11 = fma2(h1.x, ub.x, a11);
            a11 = fma2(h1.y, ub.y, a11);
        }

        float lo, hi;
        float z00, z01, z10, z11;
        unpack2(a00, lo, hi); z00 = lo + hi;
        unpack2(a01, lo, hi); z01 = lo + hi;
        unpack2(a10, lo, hi); z10 = lo + hi;
        unpack2(a11, lo, hi); z11 = lo + hi;

        float f0 = 0.0f, f1 = 0.0f, o0 = 0.0f, o1 = 0.0f;
        if (t < 128) {
            // (i, g) of cell t: write only the product p = i*g
            float i0 = sigmoid_f(z00), i1 = sigmoid_f(z01);
            float g0 = tanh_f(z10),    g1 = tanh_f(z11);
            pbuf[t] = make_float2(i0 * g0, i1 * g1);
        } else {
            // (f, o) of cell t-128: keep in registers
            f0 = sigmoid_f(z00); f1 = sigmoid_f(z01);
            o0 = sigmoid_f(z10); o1 = sigmoid_f(z11);
        }
        __syncthreads();

        if (t >= 128) {
            float2 p = pbuf[cell];
            c0 = fmaf(f0, c0, p.x);
            c1 = fmaf(f1, c1, p.y);
            hl0 = o0 * tanh_f(c0);
            hl1 = o1 * tanh_f(c1);
            hrow[cell]       = hl0;
            hrow[128 + cell] = hl1;
            out[((size_t)b0 * Tv + tc) * 256 + dir * 128 + cell]       = hl0;
            out[((size_t)(b0 + 1) * Tv + tc) * 256 + dir * 128 + cell] = hl1;
        }
        __syncthreads();
        xw00 = nx00; xw01 = nx01; xw10 = nx10; xw11 = nx11;
    }

    // final states: after out[B,T,2H]: h_fw, c_fw, h_bw, c_bw (each [B,H])
    if (t >= 128) {
        size_t fin  = (size_t)Bv * Tv * 256;
        size_t hoff = fin + (size_t)(dir * 2) * (Bv * Hv);
        out[hoff + (size_t)b0 * Hv + cell]                 = hl0;
        out[hoff + (size_t)(b0 + 1) * Hv + cell]           = hl1;
        out[hoff + Bv * Hv + (size_t)b0 * Hv + cell]       = c0;
        out[hoff + Bv * Hv + (size_t)(b0 + 1) * Hv + cell] = c1;
    }
}

// ---------------------------------------------------------------------------
// Inputs (metadata order): tokens, emb, W_fw, U_fw, b_fw, W_bw, U_bw, b_bw
// Output: out[B,T,2H] fp32, then h_fw, c_fw, h_bw, c_bw (each [B,H])
// ---------------------------------------------------------------------------
extern "C" void kernel_launch(void* const* d_in, const int* in_sizes, int n_in,
                              void* d_out, int out_size)
{
    const void*  tokens = d_in[0];
    const float* emb = (const float*)d_in[1];
    const float* Wfw = (const float*)d_in[2];
    const float* Ufw = (const float*)d_in[3];
    const float* bfw = (const float*)d_in[4];
    const float* Wbw = (const float*)d_in[5];
    const float* Ubw = (const float*)d_in[6];
    const float* bbw = (const float*)d_in[7];
    float* out = (float*)d_out;

    (void)in_sizes; (void)n_in; (void)out_size;

    dim3 ggrid(Vv / 128, NW / 128);
    embw_gemm_kernel<<<ggrid, 256>>>(emb, Wfw, Wbw, bfw, bbw);

    cudaFuncSetAttribute(lstm_kernel,
                         cudaFuncAttributeMaxDynamicSharedMemorySize,
                         LSTM_SMEM_BYTES);
    lstm_kernel<<<128, 256, LSTM_SMEM_BYTES>>>(tokens, Ufw, Ubw, out);
}